// round 14
// baseline (speedup 1.0000x reference)
#include <cuda_runtime.h>
#include <math.h>
#include <stdint.h>

// Problem constants
#define Bn   8
#define Ln   4096
#define DINn 64
#define Dn   256
#define NLn  2
#define DIn  512
#define DSn  16
#define DCn  4
#define DTRn 16
#define Mrows (Bn * Ln)   // 32768

#define C_CHUNKS 64
#define CH_LEN   64       // Ln / C_CHUNKS
#define NCH      (Bn * DIn * DSn)   // 65536

// ---------------------------------------------------------------------------
// Scratch (device globals — no runtime allocation allowed)
// ---------------------------------------------------------------------------
__device__ float g_h    [Mrows * Dn];
__device__ float g_t0   [Mrows * Dn];
__device__ float g_xz   [Mrows * 2 * DIn];
__device__ float g_u    [Mrows * DIn];
__device__ float g_dt   [Mrows * DIn];
__device__ float g_xdbc [Mrows * 48];
__device__ float g_y    [Mrows * DIn];
__device__ float g_P    [(C_CHUNKS - 1) * NCH];
__device__ float g_h0   [(C_CHUNKS - 1) * NCH];
__device__ float g_hini [C_CHUNKS * NCH];
__device__ float g_logit[Mrows];
__device__ float g_part [Bn * 16 * Dn];

// ---------------------------------------------------------------------------
// Helpers
// ---------------------------------------------------------------------------
__device__ __forceinline__ float softplus_f(float x) {
    return fmaxf(x, 0.f) + log1pf(__expf(-fabsf(x)));
}
__device__ __forceinline__ float silu_f(float x) {
    return x / (1.f + __expf(-x));
}
__device__ __forceinline__ float to_tf32(float x) {
    float r;
    asm("cvt.rna.tf32.f32 %0, %1;" : "=f"(r) : "f"(x));
    return r;
}
__device__ __forceinline__ float ex2f(float x) {
    float r;
    asm("ex2.approx.ftz.f32 %0, %1;" : "=f"(r) : "f"(x));
    return r;
}
#define LOG2E 1.4426950408889634f
__device__ __forceinline__ void mma8(float* d,
                                     float a0, float a1, float a2, float a3,
                                     float b0, float b1) {
    asm volatile(
        "mma.sync.aligned.m16n8k8.row.col.f32.tf32.tf32.f32 "
        "{%0,%1,%2,%3},{%4,%5,%6,%7},{%8,%9},{%0,%1,%2,%3};"
        : "+f"(d[0]), "+f"(d[1]), "+f"(d[2]), "+f"(d[3])
        : "r"(__float_as_uint(a0)), "r"(__float_as_uint(a1)),
          "r"(__float_as_uint(a2)), "r"(__float_as_uint(a3)),
          "r"(__float_as_uint(b0)), "r"(__float_as_uint(b1)));
}

#define SPAD 24

// ---------------------------------------------------------------------------
// tf32_gemm64: 128x64 tile, 256 threads, warp tile 32x32 (MF=2 m-frags).
// 32 accumulators/thread -> ~70 regs -> 3 CTAs/SM (24 warps).
// Requires N%64==0, K%16==0, M%128==0.  EPI: 0 store, 1 +bias.
// ---------------------------------------------------------------------------
template <int EPI>
__global__ void __launch_bounds__(256, 3) tf32_gemm64(
    int K,
    const float* __restrict__ A, int lda,
    const float* __restrict__ W,
    const float* __restrict__ bias,
    float* __restrict__ C, int ldc)
{
    __shared__ float As[2][128][SPAD];
    __shared__ float Ws[2][64][SPAD];

    const int tid  = threadIdx.x;
    const int wid  = tid >> 5, lane = tid & 31;
    const int wm   = (wid >> 1) * 32;     // 4 m-groups of 32
    const int wn   = (wid & 1) * 32;      // 2 n-groups of 32
    const int gr   = lane >> 2;
    const int gc   = lane & 3;
    const int m0   = blockIdx.y * 128;
    const int n0   = blockIdx.x * 64;

    const int lr0 = tid >> 2;             // 0..63
    const int lj  = tid & 3;
    const int pb  = (lj & 2) * 4 + (lj & 1);

    const float* Ag = A + (size_t)(m0 + lr0) * lda + lj * 4;
    const float* Wg = W + (size_t)(n0 + lr0) * K + lj * 4;

    float acc[2][4][4];
    #pragma unroll
    for (int i = 0; i < 2; i++)
        #pragma unroll
        for (int j = 0; j < 4; j++)
            #pragma unroll
            for (int t = 0; t < 4; t++) acc[i][j][t] = 0.f;

    float4 ra0, ra1, rw0;

    ra0 = *(const float4*)(Ag);
    ra1 = *(const float4*)(Ag + (size_t)64 * lda);
    rw0 = *(const float4*)(Wg);
    {
        As[0][lr0     ][pb]     = to_tf32(ra0.x);
        As[0][lr0     ][pb + 2] = to_tf32(ra0.y);
        As[0][lr0     ][pb + 4] = to_tf32(ra0.z);
        As[0][lr0     ][pb + 6] = to_tf32(ra0.w);
        As[0][lr0 + 64][pb]     = to_tf32(ra1.x);
        As[0][lr0 + 64][pb + 2] = to_tf32(ra1.y);
        As[0][lr0 + 64][pb + 4] = to_tf32(ra1.z);
        As[0][lr0 + 64][pb + 6] = to_tf32(ra1.w);
        Ws[0][lr0][pb]     = to_tf32(rw0.x);
        Ws[0][lr0][pb + 2] = to_tf32(rw0.y);
        Ws[0][lr0][pb + 4] = to_tf32(rw0.z);
        Ws[0][lr0][pb + 6] = to_tf32(rw0.w);
    }
    __syncthreads();

    int buf = 0;
    for (int k0 = 16; k0 < K; k0 += 16) {
        ra0 = *(const float4*)(Ag + k0);
        ra1 = *(const float4*)(Ag + (size_t)64 * lda + k0);
        rw0 = *(const float4*)(Wg + k0);

        #pragma unroll
        for (int ks = 0; ks < 2; ks++) {
            float2 alo[2], ahi[2], bfr[4];
            #pragma unroll
            for (int fm = 0; fm < 2; fm++) {
                alo[fm] = *(const float2*)&As[buf][wm + fm * 16 + gr    ][ks * 8 + 2 * gc];
                ahi[fm] = *(const float2*)&As[buf][wm + fm * 16 + gr + 8][ks * 8 + 2 * gc];
            }
            #pragma unroll
            for (int fn = 0; fn < 4; fn++)
                bfr[fn] = *(const float2*)&Ws[buf][wn + fn * 8 + gr][ks * 8 + 2 * gc];
            #pragma unroll
            for (int fm = 0; fm < 2; fm++)
                #pragma unroll
                for (int fn = 0; fn < 4; fn++)
                    mma8(acc[fm][fn], alo[fm].x, ahi[fm].x, alo[fm].y, ahi[fm].y,
                         bfr[fn].x, bfr[fn].y);
        }

        const int nb = buf ^ 1;
        As[nb][lr0     ][pb]     = to_tf32(ra0.x);
        As[nb][lr0     ][pb + 2] = to_tf32(ra0.y);
        As[nb][lr0     ][pb + 4] = to_tf32(ra0.z);
        As[nb][lr0     ][pb + 6] = to_tf32(ra0.w);
        As[nb][lr0 + 64][pb]     = to_tf32(ra1.x);
        As[nb][lr0 + 64][pb + 2] = to_tf32(ra1.y);
        As[nb][lr0 + 64][pb + 4] = to_tf32(ra1.z);
        As[nb][lr0 + 64][pb + 6] = to_tf32(ra1.w);
        Ws[nb][lr0][pb]     = to_tf32(rw0.x);
        Ws[nb][lr0][pb + 2] = to_tf32(rw0.y);
        Ws[nb][lr0][pb + 4] = to_tf32(rw0.z);
        Ws[nb][lr0][pb + 6] = to_tf32(rw0.w);
        __syncthreads();
        buf = nb;
    }

    #pragma unroll
    for (int ks = 0; ks < 2; ks++) {
        float2 alo[2], ahi[2], bfr[4];
        #pragma unroll
        for (int fm = 0; fm < 2; fm++) {
            alo[fm] = *(const float2*)&As[buf][wm + fm * 16 + gr    ][ks * 8 + 2 * gc];
            ahi[fm] = *(const float2*)&As[buf][wm + fm * 16 + gr + 8][ks * 8 + 2 * gc];
        }
        #pragma unroll
        for (int fn = 0; fn < 4; fn++)
            bfr[fn] = *(const float2*)&Ws[buf][wn + fn * 8 + gr][ks * 8 + 2 * gc];
        #pragma unroll
        for (int fm = 0; fm < 2; fm++)
            #pragma unroll
            for (int fn = 0; fn < 4; fn++)
                mma8(acc[fm][fn], alo[fm].x, ahi[fm].x, alo[fm].y, ahi[fm].y,
                     bfr[fn].x, bfr[fn].y);
    }

    #pragma unroll
    for (int fm = 0; fm < 2; fm++) {
        const int r0 = m0 + wm + fm * 16 + gr;
        #pragma unroll
        for (int fn = 0; fn < 4; fn++) {
            const int c0 = n0 + wn + fn * 8 + 2 * gc;
            float v0 = acc[fm][fn][0], v1 = acc[fm][fn][1];
            float v2 = acc[fm][fn][2], v3 = acc[fm][fn][3];
            if (EPI == 1) {
                v0 += bias[c0]; v1 += bias[c0 + 1];
                v2 += bias[c0]; v3 += bias[c0 + 1];
            }
            *(float2*)&C[(size_t)r0 * ldc + c0]       = make_float2(v0, v1);
            *(float2*)&C[(size_t)(r0 + 8) * ldc + c0] = make_float2(v2, v3);
        }
    }
}

// ---------------------------------------------------------------------------
// Guarded 128-wide TF32 GEMM (R4-proven) — used only for Wx (N=48).
// ---------------------------------------------------------------------------
__global__ void __launch_bounds__(256, 2) tf32_gemm_g(
    int N, int K,
    const float* __restrict__ A, int lda,
    const float* __restrict__ W,
    float* __restrict__ C, int ldc)
{
    __shared__ float As[2][128][SPAD];
    __shared__ float Ws[2][128][SPAD];

    const int tid  = threadIdx.x;
    const int wid  = tid >> 5, lane = tid & 31;
    const int wm   = (wid >> 2) * 64;
    const int wn   = (wid & 3) * 32;
    const int gr   = lane >> 2;
    const int gc   = lane & 3;
    const int m0   = blockIdx.y * 128;
    const int n0   = blockIdx.x * 128;

    const int lr0 = tid >> 2;
    const int lj  = tid & 3;
    const int pb  = (lj & 2) * 4 + (lj & 1);

    const float* Ag = A + (size_t)(m0 + lr0) * lda + lj * 4;
    const float* Wg = W + (size_t)(n0 + lr0) * K + lj * 4;
    const bool wok0 = (n0 + lr0) < N;
    const bool wok1 = (n0 + lr0 + 64) < N;

    float acc[4][4][4];
    #pragma unroll
    for (int i = 0; i < 4; i++)
        #pragma unroll
        for (int j = 0; j < 4; j++)
            #pragma unroll
            for (int t = 0; t < 4; t++) acc[i][j][t] = 0.f;

    float4 ra0, ra1, rw0, rw1;
    const float4 z4 = make_float4(0.f, 0.f, 0.f, 0.f);

    ra0 = *(const float4*)(Ag);
    ra1 = *(const float4*)(Ag + (size_t)64 * lda);
    rw0 = wok0 ? *(const float4*)(Wg) : z4;
    rw1 = wok1 ? *(const float4*)(Wg + (size_t)64 * K) : z4;
    {
        As[0][lr0     ][pb]     = to_tf32(ra0.x);
        As[0][lr0     ][pb + 2] = to_tf32(ra0.y);
        As[0][lr0     ][pb + 4] = to_tf32(ra0.z);
        As[0][lr0     ][pb + 6] = to_tf32(ra0.w);
        As[0][lr0 + 64][pb]     = to_tf32(ra1.x);
        As[0][lr0 + 64][pb + 2] = to_tf32(ra1.y);
        As[0][lr0 + 64][pb + 4] = to_tf32(ra1.z);
        As[0][lr0 + 64][pb + 6] = to_tf32(ra1.w);
        Ws[0][lr0     ][pb]     = to_tf32(rw0.x);
        Ws[0][lr0     ][pb + 2] = to_tf32(rw0.y);
        Ws[0][lr0     ][pb + 4] = to_tf32(rw0.z);
        Ws[0][lr0     ][pb + 6] = to_tf32(rw0.w);
        Ws[0][lr0 + 64][pb]     = to_tf32(rw1.x);
        Ws[0][lr0 + 64][pb + 2] = to_tf32(rw1.y);
        Ws[0][lr0 + 64][pb + 4] = to_tf32(rw1.z);
        Ws[0][lr0 + 64][pb + 6] = to_tf32(rw1.w);
    }
    __syncthreads();

    int buf = 0;
    for (int k0 = 16; k0 < K; k0 += 16) {
        ra0 = *(const float4*)(Ag + k0);
        ra1 = *(const float4*)(Ag + (size_t)64 * lda + k0);
        rw0 = wok0 ? *(const float4*)(Wg + k0) : z4;
        rw1 = wok1 ? *(const float4*)(Wg + (size_t)64 * K + k0) : z4;

        #pragma unroll
        for (int ks = 0; ks < 2; ks++) {
            float2 alo[4], ahi[4], bfr[4];
            #pragma unroll
            for (int fm = 0; fm < 4; fm++) {
                alo[fm] = *(const float2*)&As[buf][wm + fm * 16 + gr    ][ks * 8 + 2 * gc];
                ahi[fm] = *(const float2*)&As[buf][wm + fm * 16 + gr + 8][ks * 8 + 2 * gc];
            }
            #pragma unroll
            for (int fn = 0; fn < 4; fn++)
                bfr[fn] = *(const float2*)&Ws[buf][wn + fn * 8 + gr][ks * 8 + 2 * gc];
            #pragma unroll
            for (int fm = 0; fm < 4; fm++)
                #pragma unroll
                for (int fn = 0; fn < 4; fn++)
                    mma8(acc[fm][fn], alo[fm].x, ahi[fm].x, alo[fm].y, ahi[fm].y,
                         bfr[fn].x, bfr[fn].y);
        }

        const int nb = buf ^ 1;
        As[nb][lr0     ][pb]     = to_tf32(ra0.x);
        As[nb][lr0     ][pb + 2] = to_tf32(ra0.y);
        As[nb][lr0     ][pb + 4] = to_tf32(ra0.z);
        As[nb][lr0     ][pb + 6] = to_tf32(ra0.w);
        As[nb][lr0 + 64][pb]     = to_tf32(ra1.x);
        As[nb][lr0 + 64][pb + 2] = to_tf32(ra1.y);
        As[nb][lr0 + 64][pb + 4] = to_tf32(ra1.z);
        As[nb][lr0 + 64][pb + 6] = to_tf32(ra1.w);
        Ws[nb][lr0     ][pb]     = to_tf32(rw0.x);
        Ws[nb][lr0     ][pb + 2] = to_tf32(rw0.y);
        Ws[nb][lr0     ][pb + 4] = to_tf32(rw0.z);
        Ws[nb][lr0     ][pb + 6] = to_tf32(rw0.w);
        Ws[nb][lr0 + 64][pb]     = to_tf32(rw1.x);
        Ws[nb][lr0 + 64][pb + 2] = to_tf32(rw1.y);
        Ws[nb][lr0 + 64][pb + 4] = to_tf32(rw1.z);
        Ws[nb][lr0 + 64][pb + 6] = to_tf32(rw1.w);
        __syncthreads();
        buf = nb;
    }

    #pragma unroll
    for (int ks = 0; ks < 2; ks++) {
        float2 alo[4], ahi[4], bfr[4];
        #pragma unroll
        for (int fm = 0; fm < 4; fm++) {
            alo[fm] = *(const float2*)&As[buf][wm + fm * 16 + gr    ][ks * 8 + 2 * gc];
            ahi[fm] = *(const float2*)&As[buf][wm + fm * 16 + gr + 8][ks * 8 + 2 * gc];
        }
        #pragma unroll
        for (int fn = 0; fn < 4; fn++)
            bfr[fn] = *(const float2*)&Ws[buf][wn + fn * 8 + gr][ks * 8 + 2 * gc];
        #pragma unroll
        for (int fm = 0; fm < 4; fm++)
            #pragma unroll
            for (int fn = 0; fn < 4; fn++)
                mma8(acc[fm][fn], alo[fm].x, ahi[fm].x, alo[fm].y, ahi[fm].y,
                     bfr[fn].x, bfr[fn].y);
    }

    #pragma unroll
    for (int fm = 0; fm < 4; fm++) {
        const int r0 = m0 + wm + fm * 16 + gr;
        #pragma unroll
        for (int fn = 0; fn < 4; fn++) {
            const int c0 = n0 + wn + fn * 8 + 2 * gc;
            if (c0 < N) {
                *(float2*)&C[(size_t)r0 * ldc + c0] =
                    make_float2(acc[fm][fn][0], acc[fm][fn][1]);
                *(float2*)&C[(size_t)(r0 + 8) * ldc + c0] =
                    make_float2(acc[fm][fn][2], acc[fm][fn][3]);
            }
        }
    }
}

// ---------------------------------------------------------------------------
// SIMT SGEMM for dt (N=512, K=16). softplus(+bias) epilogue.
// ---------------------------------------------------------------------------
__global__ void __launch_bounds__(256, 2) sgemm_dt(
    int N, int K,
    const float* __restrict__ A, int lda,
    const float* __restrict__ W,
    const float* __restrict__ bias,
    float* __restrict__ C, int ldc)
{
    __shared__ __align__(16) float As[8][132];
    __shared__ __align__(16) float Ws2[8][132];

    const int tid = threadIdx.x;
    const int tx = tid & 15;
    const int ty = tid >> 4;
    const int m0 = blockIdx.y * 128;
    const int n0 = blockIdx.x * 128;

    const int lr = tid >> 1;
    const int lk = (tid & 1) * 4;

    float acc[8][8];
    #pragma unroll
    for (int i = 0; i < 8; i++)
        #pragma unroll
        for (int j = 0; j < 8; j++) acc[i][j] = 0.f;

    const float* Aptr = A + (size_t)(m0 + lr) * lda + lk;
    const int wn = n0 + lr;
    const float* Wptr = W + (size_t)wn * K + lk;
    const bool wok = (wn < N);

    for (int k0 = 0; k0 < K; k0 += 8) {
        float4 av = *(const float4*)(Aptr + k0);
        As[lk + 0][lr] = av.x; As[lk + 1][lr] = av.y;
        As[lk + 2][lr] = av.z; As[lk + 3][lr] = av.w;

        float4 wv = make_float4(0.f, 0.f, 0.f, 0.f);
        if (wok) wv = *(const float4*)(Wptr + k0);
        Ws2[lk + 0][lr] = wv.x; Ws2[lk + 1][lr] = wv.y;
        Ws2[lk + 2][lr] = wv.z; Ws2[lk + 3][lr] = wv.w;

        __syncthreads();
        #pragma unroll
        for (int k = 0; k < 8; k++) {
            float a[8], bb[8];
            *(float4*)&a[0]  = *(const float4*)&As[k][ty * 4];
            *(float4*)&a[4]  = *(const float4*)&As[k][64 + ty * 4];
            *(float4*)&bb[0] = *(const float4*)&Ws2[k][tx * 4];
            *(float4*)&bb[4] = *(const float4*)&Ws2[k][64 + tx * 4];
            #pragma unroll
            for (int i = 0; i < 8; i++)
                #pragma unroll
                for (int j = 0; j < 8; j++)
                    acc[i][j] = fmaf(a[i], bb[j], acc[i][j]);
        }
        __syncthreads();
    }

    #pragma unroll
    for (int i = 0; i < 8; i++) {
        const int r = m0 + ((i < 4) ? (ty * 4 + i) : (64 + ty * 4 + i - 4));
        #pragma unroll
        for (int j = 0; j < 8; j++) {
            const int c = n0 + ((j < 4) ? (tx * 4 + j) : (64 + tx * 4 + j - 4));
            if (c < N) {
                float v = acc[i][j] + bias[c];
                C[(size_t)r * ldc + c] = softplus_f(v);
            }
        }
    }
}

// ---------------------------------------------------------------------------
// Depthwise causal conv (DC=4) + bias + SiLU — l-vectorized (R13-proven).
// ---------------------------------------------------------------------------
__global__ void conv_silu_kernel(const float* __restrict__ xz,
                                 const float* __restrict__ w,
                                 const float* __restrict__ cb,
                                 float* __restrict__ u)
{
    const int idx = blockIdx.x * blockDim.x + threadIdx.x;
    if (idx >= Mrows * DIn / 4) return;
    const int d   = idx & (DIn - 1);
    const int bl4 = idx >> 9;
    const int l4  = bl4 & (Ln / 4 - 1);
    const int b   = bl4 >> 10;
    const int l0  = l4 * 4;
    const int bl0 = b * Ln + l0;

    float xv[7];
    #pragma unroll
    for (int k = 0; k < 7; k++) {
        const int ll = l0 - 3 + k;
        xv[k] = (ll >= 0) ? xz[(size_t)(bl0 - 3 + k) * (2 * DIn) + d] : 0.f;
    }
    const float w0 = w[d * 4 + 0], w1 = w[d * 4 + 1];
    const float w2 = w[d * 4 + 2], w3 = w[d * 4 + 3];
    const float cbv = cb[d];

    #pragma unroll
    for (int j = 0; j < 4; j++) {
        float acc = cbv;
        acc = fmaf(w0, xv[j + 0], acc);
        acc = fmaf(w1, xv[j + 1], acc);
        acc = fmaf(w2, xv[j + 2], acc);
        acc = fmaf(w3, xv[j + 3], acc);
        u[(size_t)(bl0 + j) * DIn + d] = silu_f(acc);
    }
}

// ---------------------------------------------------------------------------
// LayerNorm warp-per-row (R13-proven).
// ---------------------------------------------------------------------------
__global__ void ln256_kernel(const float* __restrict__ in, float* __restrict__ out,
                             const float* __restrict__ g, const float* __restrict__ b)
{
    const int warp = threadIdx.x >> 5;
    const int lane = threadIdx.x & 31;
    const int row  = blockIdx.x * 8 + warp;
    const float* r = in + (size_t)row * 256;

    float4 v0 = *(const float4*)(r + lane * 4);
    float4 v1 = *(const float4*)(r + 128 + lane * 4);

    float s  = v0.x + v0.y + v0.z + v0.w + v1.x + v1.y + v1.z + v1.w;
    float sq = v0.x * v0.x + v0.y * v0.y + v0.z * v0.z + v0.w * v0.w
             + v1.x * v1.x + v1.y * v1.y + v1.z * v1.z + v1.w * v1.w;
    #pragma unroll
    for (int o = 16; o > 0; o >>= 1) {
        s  += __shfl_xor_sync(~0u, s, o);
        sq += __shfl_xor_sync(~0u, sq, o);
    }
    const float mean = s * (1.f / 256.f);
    const float var  = sq * (1.f / 256.f) - mean * mean;
    const float rstd = rsqrtf(var + 1e-5f);

    const float4 g0 = *(const float4*)(g + lane * 4);
    const float4 g1 = *(const float4*)(g + 128 + lane * 4);
    const float4 b0 = *(const float4*)(b + lane * 4);
    const float4 b1 = *(const float4*)(b + 128 + lane * 4);

    float4 o0, o1;
    o0.x = (v0.x - mean) * rstd * g0.x + b0.x;
    o0.y = (v0.y - mean) * rstd * g0.y + b0.y;
    o0.z = (v0.z - mean) * rstd * g0.z + b0.z;
    o0.w = (v0.w - mean) * rstd * g0.w + b0.w;
    o1.x = (v1.x - mean) * rstd * g1.x + b1.x;
    o1.y = (v1.y - mean) * rstd * g1.y + b1.y;
    o1.z = (v1.z - mean) * rstd * g1.z + b1.z;
    o1.w = (v1.w - mean) * rstd * g1.w + b1.w;

    float* ro = out + (size_t)row * 256;
    *(float4*)(ro + lane * 4)       = o0;
    *(float4*)(ro + 128 + lane * 4) = o1;
}

// ---------------------------------------------------------------------------
// Selective scan, thread-per-d (R11/R12-proven), C_CHUNKS=64.
// ---------------------------------------------------------------------------
#define SCH2 16

__global__ void __launch_bounds__(128) scan_carry_kernel(
    const float* __restrict__ u, const float* __restrict__ dt,
    const float* __restrict__ xdbc, const float* __restrict__ A_log,
    float* __restrict__ Pout, float* __restrict__ h0out)
{
    __shared__ float s_dt[SCH2][128], s_u[SCH2][128];
    __shared__ float s_B[SCH2][16];

    const int tid = threadIdx.x;
    const int c   = blockIdx.x >> 5;          // 0..C-2
    const int rem = blockIdx.x & 31;
    const int b   = rem >> 2;
    const int dg  = rem & 3;
    const int d   = dg * 128 + tid;

    float A2[16];
    #pragma unroll
    for (int s = 0; s < 16; s++)
        A2[s] = -__expf(A_log[d * 16 + s]) * LOG2E;

    float P[16], h[16];
    #pragma unroll
    for (int s = 0; s < 16; s++) { P[s] = 1.f; h[s] = 0.f; }

    const size_t base_bl = (size_t)b * Ln + (size_t)c * CH_LEN;
    const int doff = dg * 128;

    for (int l0 = 0; l0 < CH_LEN; l0 += SCH2) {
        #pragma unroll
        for (int r = 0; r < SCH2; r++) {
            const size_t bl = base_bl + l0 + r;
            s_dt[r][tid] = dt[bl * DIn + doff + tid];
            s_u [r][tid] = u [bl * DIn + doff + tid];
        }
        for (int i = tid; i < SCH2 * 16; i += 128) {
            const int r = i >> 4, cc = i & 15;
            s_B[r][cc] = xdbc[(base_bl + l0 + r) * 48 + 16 + cc];
        }
        __syncthreads();

        for (int i = 0; i < SCH2; i++) {
            const float dtv = s_dt[i][tid];
            const float x   = dtv * s_u[i][tid];
            float Bv[16];
            *(float4*)&Bv[0]  = *(const float4*)&s_B[i][0];
            *(float4*)&Bv[4]  = *(const float4*)&s_B[i][4];
            *(float4*)&Bv[8]  = *(const float4*)&s_B[i][8];
            *(float4*)&Bv[12] = *(const float4*)&s_B[i][12];
            #pragma unroll
            for (int s = 0; s < 16; s++) {
                const float dA = ex2f(dtv * A2[s]);
                P[s] *= dA;
                h[s] = fmaf(h[s], dA, x * Bv[s]);
            }
        }
        __syncthreads();
    }

    const size_t chb = (size_t)(b * DIn + d) * DSn;
    #pragma unroll
    for (int s = 0; s < 16; s++) {
        Pout [(size_t)c * NCH + chb + s] = P[s];
        h0out[(size_t)c * NCH + chb + s] = h[s];
    }
}

__global__ void scan_fix_kernel(const float* __restrict__ P,
                                const float* __restrict__ h0,
                                float* __restrict__ hini)
{
    const int ch = blockIdx.x * blockDim.x + threadIdx.x;
    float h = 0.f;
    hini[ch] = 0.f;
    #pragma unroll 4
    for (int c = 1; c < C_CHUNKS; c++) {
        h = fmaf(P[(size_t)(c - 1) * NCH + ch], h, h0[(size_t)(c - 1) * NCH + ch]);
        hini[(size_t)c * NCH + ch] = h;
    }
}

__global__ void __launch_bounds__(128) scan_main_kernel(
    const float* __restrict__ u, const float* __restrict__ dt,
    const float* __restrict__ xz, const float* __restrict__ xdbc,
    const float* __restrict__ A_log, const float* __restrict__ Dp,
    const float* __restrict__ hini,
    float* __restrict__ y)
{
    __shared__ float s_dt[SCH2][128], s_u[SCH2][128], s_z[SCH2][128];
    __shared__ float s_B[SCH2][16], s_C[SCH2][16];

    const int tid = threadIdx.x;
    const int c   = blockIdx.x >> 5;          // 0..C-1
    const int rem = blockIdx.x & 31;
    const int b   = rem >> 2;
    const int dg  = rem & 3;
    const int d   = dg * 128 + tid;

    float A2[16];
    #pragma unroll
    for (int s = 0; s < 16; s++)
        A2[s] = -__expf(A_log[d * 16 + s]) * LOG2E;
    const float dpv = Dp[d];

    const size_t chb = (size_t)(b * DIn + d) * DSn;
    float h[16];
    *(float4*)&h[0]  = *(const float4*)&hini[(size_t)c * NCH + chb];
    *(float4*)&h[4]  = *(const float4*)&hini[(size_t)c * NCH + chb + 4];
    *(float4*)&h[8]  = *(const float4*)&hini[(size_t)c * NCH + chb + 8];
    *(float4*)&h[12] = *(const float4*)&hini[(size_t)c * NCH + chb + 12];

    const size_t base_bl = (size_t)b * Ln + (size_t)c * CH_LEN;
    const int doff = dg * 128;

    for (int l0 = 0; l0 < CH_LEN; l0 += SCH2) {
        #pragma unroll
        for (int r = 0; r < SCH2; r++) {
            const size_t bl = base_bl + l0 + r;
            s_dt[r][tid] = dt[bl * DIn + doff + tid];
            s_u [r][tid] = u [bl * DIn + doff + tid];
            s_z [r][tid] = xz[bl * (2 * DIn) + DIn + doff + tid];
        }
        for (int i = tid; i < SCH2 * 16; i += 128) {
            const int r = i >> 4, cc = i & 15;
            const size_t bl = base_bl + l0 + r;
            s_B[r][cc] = xdbc[bl * 48 + 16 + cc];
            s_C[r][cc] = xdbc[bl * 48 + 32 + cc];
        }
        __syncthreads();

        for (int i = 0; i < SCH2; i++) {
            const float dtv = s_dt[i][tid];
            const float uv  = s_u[i][tid];
            const float zv  = s_z[i][tid];
            const float x   = dtv * uv;
            float Bv[16], Cv[16];
            *(float4*)&Bv[0]  = *(const float4*)&s_B[i][0];
            *(float4*)&Bv[4]  = *(const float4*)&s_B[i][4];
            *(float4*)&Bv[8]  = *(const float4*)&s_B[i][8];
            *(float4*)&Bv[12] = *(const float4*)&s_B[i][12];
            *(float4*)&Cv[0]  = *(const float4*)&s_C[i][0];
            *(float4*)&Cv[4]  = *(const float4*)&s_C[i][4];
            *(float4*)&Cv[8]  = *(const float4*)&s_C[i][8];
            *(float4*)&Cv[12] = *(const float4*)&s_C[i][12];
            float yv = 0.f;
            #pragma unroll
            for (int s = 0; s < 16; s++) {
                const float dA = ex2f(dtv * A2[s]);
                h[s] = fmaf(h[s], dA, x * Bv[s]);
                yv = fmaf(h[s], Cv[s], yv);
            }
            yv = (yv + uv * dpv) * silu_f(zv);
            y[(base_bl + l0 + i) * DIn + doff + tid] = yv;
        }
        __syncthreads();
    }
}

// ---------------------------------------------------------------------------
// Pooling (split, R4-proven).
// ---------------------------------------------------------------------------
__global__ void pool_logit_kernel(const float* __restrict__ h,
                                  const float* __restrict__ wa,
                                  const float* __restrict__ ba,
                                  float* __restrict__ logit)
{
    const int wid_in_blk = threadIdx.x >> 5;
    const int lane = threadIdx.x & 31;
    const int row = blockIdx.x * 8 + wid_in_blk;
    const float* r = h + (size_t)row * 256;
    float acc = 0.f;
    #pragma unroll
    for (int k = 0; k < 2; k++) {
        const float4 hv = *(const float4*)(r + k * 128 + lane * 4);
        const float4 wv = *(const float4*)(wa + k * 128 + lane * 4);
        acc += hv.x * wv.x + hv.y * wv.y + hv.z * wv.z + hv.w * wv.w;
    }
    #pragma unroll
    for (int o = 16; o > 0; o >>= 1) acc += __shfl_xor_sync(~0u, acc, o);
    if (lane == 0) logit[row] = acc + ba[0];
}

__global__ void __launch_bounds__(1024) pool_softmax_kernel(float* __restrict__ logit)
{
    __shared__ float s_red[32];
    const int b = blockIdx.x, tid = threadIdx.x;
    float* lg = logit + b * Ln;

    float mx = -1e30f;
    float v[4];
    #pragma unroll
    for (int k = 0; k < 4; k++) {
        v[k] = lg[tid + k * 1024];
        mx = fmaxf(mx, v[k]);
    }
    #pragma unroll
    for (int o = 16; o > 0; o >>= 1) mx = fmaxf(mx, __shfl_xor_sync(~0u, mx, o));
    if ((tid & 31) == 0) s_red[tid >> 5] = mx;
    __syncthreads();
    if (tid < 32) {
        float t = s_red[tid];
        #pragma unroll
        for (int o = 16; o > 0; o >>= 1) t = fmaxf(t, __shfl_xor_sync(~0u, t, o));
        s_red[tid] = t;
    }
    __syncthreads();
    mx = s_red[0];
    __syncthreads();

    float sum = 0.f;
    #pragma unroll
    for (int k = 0; k < 4; k++) {
        v[k] = __expf(v[k] - mx);
        sum += v[k];
    }
    #pragma unroll
    for (int o = 16; o > 0; o >>= 1) sum += __shfl_xor_sync(~0u, sum, o);
    if ((tid & 31) == 0) s_red[tid >> 5] = sum;
    __syncthreads();
    if (tid < 32) {
        float t = s_red[tid];
        #pragma unroll
        for (int o = 16; o > 0; o >>= 1) t += __shfl_xor_sync(~0u, t, o);
        s_red[tid] = t;
    }
    __syncthreads();
    const float inv = 1.f / s_red[0];
    #pragma unroll
    for (int k = 0; k < 4; k++) lg[tid + k * 1024] = v[k] * inv;
}

__global__ void pool_wsum_kernel(const float* __restrict__ h,
                                 const float* __restrict__ p,
                                 float* __restrict__ part)
{
    const int b = blockIdx.x >> 4;
    const int sp = blockIdx.x & 15;
    const int tid = threadIdx.x;
    const size_t base = ((size_t)b * Ln + sp * 256) * 256;
    const float* pp = p + b * Ln + sp * 256;
    float acc = 0.f;
    for (int l = 0; l < 256; l++)
        acc = fmaf(pp[l], h[base + (size_t)l * 256 + tid], acc);
    part[(size_t)(b * 16 + sp) * 256 + tid] = acc;
}

__global__ void pool_final_kernel(const float* __restrict__ part,
                                  const float* __restrict__ Wf,
                                  const float* __restrict__ bf,
                                  float* __restrict__ out)
{
    __shared__ float s_red[8];
    const int b = blockIdx.x, tid = threadIdx.x;
    float pooled = 0.f;
    #pragma unroll
    for (int sp = 0; sp < 16; sp++)
        pooled += part[(size_t)(b * 16 + sp) * 256 + tid];
    float val = pooled * Wf[tid];
    #pragma unroll
    for (int o = 16; o > 0; o >>= 1) val += __shfl_xor_sync(~0u, val, o);
    if ((tid & 31) == 0) s_red[tid >> 5] = val;
    __syncthreads();
    if (tid == 0) {
        float tot = 0.f;
        #pragma unroll
        for (int i = 0; i < 8; i++) tot += s_red[i];
        out[b] = tot + bf[0];
    }
}

// ---------------------------------------------------------------------------
// Launch
// ---------------------------------------------------------------------------
extern "C" void kernel_launch(void* const* d_in, const int* in_sizes, int n_in,
                              void* d_out, int out_size)
{
    const float* x      = (const float*)d_in[0];
    const float* Wp     = (const float*)d_in[1];
    const float* bp     = (const float*)d_in[2];
    const float* g0     = (const float*)d_in[3];
    const float* b0     = (const float*)d_in[4];
    const float* Wi     = (const float*)d_in[5];
    const float* conv_w = (const float*)d_in[6];
    const float* conv_b = (const float*)d_in[7];
    const float* Wx     = (const float*)d_in[8];
    const float* Wdt    = (const float*)d_in[9];
    const float* bdt    = (const float*)d_in[10];
    const float* A_log  = (const float*)d_in[11];
    const float* Dp     = (const float*)d_in[12];
    const float* Wo     = (const float*)d_in[13];
    const float* ln_g   = (const float*)d_in[14];
    const float* ln_b   = (const float*)d_in[15];
    const float* wa     = (const float*)d_in[16];
    const float* ba     = (const float*)d_in[17];
    const float* Wf     = (const float*)d_in[18];
    const float* bf     = (const float*)d_in[19];

    float *p_h, *p_t0, *p_xz, *p_u, *p_dt, *p_xdbc, *p_y;
    float *p_P, *p_h0, *p_hini, *p_logit, *p_part;
    cudaGetSymbolAddress((void**)&p_h,    g_h);
    cudaGetSymbolAddress((void**)&p_t0,   g_t0);
    cudaGetSymbolAddress((void**)&p_xz,   g_xz);
    cudaGetSymbolAddress((void**)&p_u,    g_u);
    cudaGetSymbolAddress((void**)&p_dt,   g_dt);
    cudaGetSymbolAddress((void**)&p_xdbc, g_xdbc);
    cudaGetSymbolAddress((void**)&p_y,    g_y);
    cudaGetSymbolAddress((void**)&p_P,    g_P);
    cudaGetSymbolAddress((void**)&p_h0,   g_h0);
    cudaGetSymbolAddress((void**)&p_hini, g_hini);
    cudaGetSymbolAddress((void**)&p_logit, g_logit);
    cudaGetSymbolAddress((void**)&p_part, g_part);

    // input projection + bias + LN
    tf32_gemm64<1><<<dim3(4, 256), 256>>>(DINn, x, DINn, Wp, bp, p_t0, Dn);
    ln256_kernel<<<Mrows / 8, 256>>>(p_t0, p_h, g0, b0);

    for (int l = 0; l < NLn; l++) {
        // xz = h @ Wi^T  (N=1024, K=256)
        tf32_gemm64<0><<<dim3(16, 256), 256>>>(Dn, p_h, Dn,
                                               Wi + (size_t)l * 2 * DIn * Dn,
                                               nullptr, p_xz, 2 * DIn);
        // depthwise causal conv + silu (l-vectorized)
        conv_silu_kernel<<<(Mrows * DIn / 4) / 256, 256>>>(
            p_xz, conv_w + (size_t)l * DIn * DCn, conv_b + (size_t)l * DIn, p_u);
        // xdbc = u @ Wx^T  (N=48, K=512) — guarded 128-wide
        tf32_gemm_g<<<dim3(1, 256), 256>>>(48, DIn, p_u, DIn,
                                           Wx + (size_t)l * 48 * DIn, p_xdbc, 48);
        // dt = softplus(dtraw @ Wdt^T + bdt)
        sgemm_dt<<<dim3(4, 256), 256>>>(DIn, DTRn, p_xdbc, 48,
                                        Wdt + (size_t)l * DIn * DTRn,
                                        bdt + (size_t)l * DIn, p_dt, DIn);
        // chunked selective scan (thread-per-d, C=64)
        scan_carry_kernel<<<32 * (C_CHUNKS - 1), 128>>>(
            p_u, p_dt, p_xdbc, A_log + (size_t)l * DIn * DSn, p_P, p_h0);
        scan_fix_kernel<<<NCH / 256, 256>>>(p_P, p_h0, p_hini);
        scan_main_kernel<<<32 * C_CHUNKS, 128>>>(
            p_u, p_dt, p_xz, p_xdbc,
            A_log + (size_t)l * DIn * DSn, Dp + (size_t)l * DIn,
            p_hini, p_y);
        // out = y @ Wo^T  (N=256, K=512), then LN
        tf32_gemm64<0><<<dim3(4, 256), 256>>>(DIn, p_y, DIn,
                                              Wo + (size_t)l * Dn * DIn,
                                              nullptr, p_t0, Dn);
        ln256_kernel<<<Mrows / 8, 256>>>(p_t0, p_h,
                                         ln_g + (size_t)l * Dn, ln_b + (size_t)l * Dn);
    }

    // pooling + final linear
    pool_logit_kernel<<<Mrows / 8, 256>>>(p_h, wa, ba, p_logit);
    pool_softmax_kernel<<<Bn, 1024>>>(p_logit);
    pool_wsum_kernel<<<Bn * 16, 256>>>(p_h, p_logit, p_part);
    pool_final_kernel<<<Bn, 256>>>(p_part, Wf, bf, (float*)d_out);
}

// round 15
// speedup vs baseline: 1.1234x; 1.1234x over previous
#include <cuda_runtime.h>
#include <math.h>
#include <stdint.h>

// Problem constants
#define Bn   8
#define Ln   4096
#define DINn 64
#define Dn   256
#define NLn  2
#define DIn  512
#define DSn  16
#define DCn  4
#define DTRn 16
#define Mrows (Bn * Ln)   // 32768

#define C_CHUNKS 64
#define CH_LEN   64       // Ln / C_CHUNKS
#define NCH      (Bn * DIn * DSn)   // 65536

// ---------------------------------------------------------------------------
// Scratch (device globals — no runtime allocation allowed)
// ---------------------------------------------------------------------------
__device__ float g_h    [Mrows * Dn];
__device__ float g_t0   [Mrows * Dn];
__device__ float g_xz   [Mrows * 2 * DIn];
__device__ float g_u    [Mrows * DIn];
__device__ float g_dt   [Mrows * DIn];
__device__ float g_xdbc [Mrows * 48];
__device__ float g_y    [Mrows * DIn];
__device__ float g_P    [(C_CHUNKS - 1) * NCH];
__device__ float g_h0   [(C_CHUNKS - 1) * NCH];
__device__ float g_hini [C_CHUNKS * NCH];
__device__ float g_logit[Mrows];
__device__ float g_part [Bn * 16 * Dn];

// ---------------------------------------------------------------------------
// Helpers
// ---------------------------------------------------------------------------
__device__ __forceinline__ float softplus_f(float x) {
    return fmaxf(x, 0.f) + log1pf(__expf(-fabsf(x)));
}
__device__ __forceinline__ float silu_f(float x) {
    return x / (1.f + __expf(-x));
}
__device__ __forceinline__ float to_tf32(float x) {
    float r;
    asm("cvt.rna.tf32.f32 %0, %1;" : "=f"(r) : "f"(x));
    return r;
}
__device__ __forceinline__ float ex2f(float x) {
    float r;
    asm("ex2.approx.ftz.f32 %0, %1;" : "=f"(r) : "f"(x));
    return r;
}
#define LOG2E 1.4426950408889634f
__device__ __forceinline__ void mma8(float* d,
                                     float a0, float a1, float a2, float a3,
                                     float b0, float b1) {
    asm volatile(
        "mma.sync.aligned.m16n8k8.row.col.f32.tf32.tf32.f32 "
        "{%0,%1,%2,%3},{%4,%5,%6,%7},{%8,%9},{%0,%1,%2,%3};"
        : "+f"(d[0]), "+f"(d[1]), "+f"(d[2]), "+f"(d[3])
        : "r"(__float_as_uint(a0)), "r"(__float_as_uint(a1)),
          "r"(__float_as_uint(a2)), "r"(__float_as_uint(a3)),
          "r"(__float_as_uint(b0)), "r"(__float_as_uint(b1)));
}

// ---------------------------------------------------------------------------
// TF32 tensor-core GEMM (R4-proven, 128x128 tile).
// ---------------------------------------------------------------------------
#define SPAD 24
template <int EPI>
__global__ void __launch_bounds__(256, 2) tf32_gemm(
    int N, int K,
    const float* __restrict__ A, int lda,
    const float* __restrict__ W,
    const float* __restrict__ bias,
    float* __restrict__ C, int ldc)
{
    __shared__ float As[2][128][SPAD];
    __shared__ float Ws[2][128][SPAD];

    const int tid  = threadIdx.x;
    const int wid  = tid >> 5, lane = tid & 31;
    const int wm   = (wid >> 2) * 64;
    const int wn   = (wid & 3) * 32;
    const int gr   = lane >> 2;
    const int gc   = lane & 3;
    const int m0   = blockIdx.y * 128;
    const int n0   = blockIdx.x * 128;

    const int lr0 = tid >> 2;
    const int lj  = tid & 3;
    const int pb  = (lj & 2) * 4 + (lj & 1);

    const float* Ag = A + (size_t)(m0 + lr0) * lda + lj * 4;
    const float* Wg = W + (size_t)(n0 + lr0) * K + lj * 4;
    const bool wok0 = (n0 + lr0) < N;
    const bool wok1 = (n0 + lr0 + 64) < N;

    float acc[4][4][4];
    #pragma unroll
    for (int i = 0; i < 4; i++)
        #pragma unroll
        for (int j = 0; j < 4; j++)
            #pragma unroll
            for (int t = 0; t < 4; t++) acc[i][j][t] = 0.f;

    float4 ra0, ra1, rw0, rw1;
    const float4 z4 = make_float4(0.f, 0.f, 0.f, 0.f);

    ra0 = *(const float4*)(Ag);
    ra1 = *(const float4*)(Ag + (size_t)64 * lda);
    rw0 = wok0 ? *(const float4*)(Wg) : z4;
    rw1 = wok1 ? *(const float4*)(Wg + (size_t)64 * K) : z4;
    {
        As[0][lr0     ][pb]     = to_tf32(ra0.x);
        As[0][lr0     ][pb + 2] = to_tf32(ra0.y);
        As[0][lr0     ][pb + 4] = to_tf32(ra0.z);
        As[0][lr0     ][pb + 6] = to_tf32(ra0.w);
        As[0][lr0 + 64][pb]     = to_tf32(ra1.x);
        As[0][lr0 + 64][pb + 2] = to_tf32(ra1.y);
        As[0][lr0 + 64][pb + 4] = to_tf32(ra1.z);
        As[0][lr0 + 64][pb + 6] = to_tf32(ra1.w);
        Ws[0][lr0     ][pb]     = to_tf32(rw0.x);
        Ws[0][lr0     ][pb + 2] = to_tf32(rw0.y);
        Ws[0][lr0     ][pb + 4] = to_tf32(rw0.z);
        Ws[0][lr0     ][pb + 6] = to_tf32(rw0.w);
        Ws[0][lr0 + 64][pb]     = to_tf32(rw1.x);
        Ws[0][lr0 + 64][pb + 2] = to_tf32(rw1.y);
        Ws[0][lr0 + 64][pb + 4] = to_tf32(rw1.z);
        Ws[0][lr0 + 64][pb + 6] = to_tf32(rw1.w);
    }
    __syncthreads();

    int buf = 0;
    for (int k0 = 16; k0 < K; k0 += 16) {
        ra0 = *(const float4*)(Ag + k0);
        ra1 = *(const float4*)(Ag + (size_t)64 * lda + k0);
        rw0 = wok0 ? *(const float4*)(Wg + k0) : z4;
        rw1 = wok1 ? *(const float4*)(Wg + (size_t)64 * K + k0) : z4;

        #pragma unroll
        for (int ks = 0; ks < 2; ks++) {
            float2 alo[4], ahi[4], bfr[4];
            #pragma unroll
            for (int fm = 0; fm < 4; fm++) {
                alo[fm] = *(const float2*)&As[buf][wm + fm * 16 + gr    ][ks * 8 + 2 * gc];
                ahi[fm] = *(const float2*)&As[buf][wm + fm * 16 + gr + 8][ks * 8 + 2 * gc];
            }
            #pragma unroll
            for (int fn = 0; fn < 4; fn++)
                bfr[fn] = *(const float2*)&Ws[buf][wn + fn * 8 + gr][ks * 8 + 2 * gc];
            #pragma unroll
            for (int fm = 0; fm < 4; fm++)
                #pragma unroll
                for (int fn = 0; fn < 4; fn++)
                    mma8(acc[fm][fn], alo[fm].x, ahi[fm].x, alo[fm].y, ahi[fm].y,
                         bfr[fn].x, bfr[fn].y);
        }

        const int nb = buf ^ 1;
        As[nb][lr0     ][pb]     = to_tf32(ra0.x);
        As[nb][lr0     ][pb + 2] = to_tf32(ra0.y);
        As[nb][lr0     ][pb + 4] = to_tf32(ra0.z);
        As[nb][lr0     ][pb + 6] = to_tf32(ra0.w);
        As[nb][lr0 + 64][pb]     = to_tf32(ra1.x);
        As[nb][lr0 + 64][pb + 2] = to_tf32(ra1.y);
        As[nb][lr0 + 64][pb + 4] = to_tf32(ra1.z);
        As[nb][lr0 + 64][pb + 6] = to_tf32(ra1.w);
        Ws[nb][lr0     ][pb]     = to_tf32(rw0.x);
        Ws[nb][lr0     ][pb + 2] = to_tf32(rw0.y);
        Ws[nb][lr0     ][pb + 4] = to_tf32(rw0.z);
        Ws[nb][lr0     ][pb + 6] = to_tf32(rw0.w);
        Ws[nb][lr0 + 64][pb]     = to_tf32(rw1.x);
        Ws[nb][lr0 + 64][pb + 2] = to_tf32(rw1.y);
        Ws[nb][lr0 + 64][pb + 4] = to_tf32(rw1.z);
        Ws[nb][lr0 + 64][pb + 6] = to_tf32(rw1.w);
        __syncthreads();
        buf = nb;
    }

    #pragma unroll
    for (int ks = 0; ks < 2; ks++) {
        float2 alo[4], ahi[4], bfr[4];
        #pragma unroll
        for (int fm = 0; fm < 4; fm++) {
            alo[fm] = *(const float2*)&As[buf][wm + fm * 16 + gr    ][ks * 8 + 2 * gc];
            ahi[fm] = *(const float2*)&As[buf][wm + fm * 16 + gr + 8][ks * 8 + 2 * gc];
        }
        #pragma unroll
        for (int fn = 0; fn < 4; fn++)
            bfr[fn] = *(const float2*)&Ws[buf][wn + fn * 8 + gr][ks * 8 + 2 * gc];
        #pragma unroll
        for (int fm = 0; fm < 4; fm++)
            #pragma unroll
            for (int fn = 0; fn < 4; fn++)
                mma8(acc[fm][fn], alo[fm].x, ahi[fm].x, alo[fm].y, ahi[fm].y,
                     bfr[fn].x, bfr[fn].y);
    }

    #pragma unroll
    for (int fm = 0; fm < 4; fm++) {
        const int r0 = m0 + wm + fm * 16 + gr;
        #pragma unroll
        for (int fn = 0; fn < 4; fn++) {
            const int c0 = n0 + wn + fn * 8 + 2 * gc;
            if (c0 < N) {
                float v0 = acc[fm][fn][0], v1 = acc[fm][fn][1];
                float v2 = acc[fm][fn][2], v3 = acc[fm][fn][3];
                if (EPI == 1) {
                    v0 += bias[c0]; v1 += bias[c0 + 1];
                    v2 += bias[c0]; v3 += bias[c0 + 1];
                }
                *(float2*)&C[(size_t)r0 * ldc + c0]       = make_float2(v0, v1);
                *(float2*)&C[(size_t)(r0 + 8) * ldc + c0] = make_float2(v2, v3);
            }
        }
    }
}

// ---------------------------------------------------------------------------
// SIMT SGEMM for dt (N=512, K=16). softplus(+bias) epilogue.
// ---------------------------------------------------------------------------
__global__ void __launch_bounds__(256, 2) sgemm_dt(
    int N, int K,
    const float* __restrict__ A, int lda,
    const float* __restrict__ W,
    const float* __restrict__ bias,
    float* __restrict__ C, int ldc)
{
    __shared__ __align__(16) float As[8][132];
    __shared__ __align__(16) float Ws2[8][132];

    const int tid = threadIdx.x;
    const int tx = tid & 15;
    const int ty = tid >> 4;
    const int m0 = blockIdx.y * 128;
    const int n0 = blockIdx.x * 128;

    const int lr = tid >> 1;
    const int lk = (tid & 1) * 4;

    float acc[8][8];
    #pragma unroll
    for (int i = 0; i < 8; i++)
        #pragma unroll
        for (int j = 0; j < 8; j++) acc[i][j] = 0.f;

    const float* Aptr = A + (size_t)(m0 + lr) * lda + lk;
    const int wn = n0 + lr;
    const float* Wptr = W + (size_t)wn * K + lk;
    const bool wok = (wn < N);

    for (int k0 = 0; k0 < K; k0 += 8) {
        float4 av = *(const float4*)(Aptr + k0);
        As[lk + 0][lr] = av.x; As[lk + 1][lr] = av.y;
        As[lk + 2][lr] = av.z; As[lk + 3][lr] = av.w;

        float4 wv = make_float4(0.f, 0.f, 0.f, 0.f);
        if (wok) wv = *(const float4*)(Wptr + k0);
        Ws2[lk + 0][lr] = wv.x; Ws2[lk + 1][lr] = wv.y;
        Ws2[lk + 2][lr] = wv.z; Ws2[lk + 3][lr] = wv.w;

        __syncthreads();
        #pragma unroll
        for (int k = 0; k < 8; k++) {
            float a[8], bb[8];
            *(float4*)&a[0]  = *(const float4*)&As[k][ty * 4];
            *(float4*)&a[4]  = *(const float4*)&As[k][64 + ty * 4];
            *(float4*)&bb[0] = *(const float4*)&Ws2[k][tx * 4];
            *(float4*)&bb[4] = *(const float4*)&Ws2[k][64 + tx * 4];
            #pragma unroll
            for (int i = 0; i < 8; i++)
                #pragma unroll
                for (int j = 0; j < 8; j++)
                    acc[i][j] = fmaf(a[i], bb[j], acc[i][j]);
        }
        __syncthreads();
    }

    #pragma unroll
    for (int i = 0; i < 8; i++) {
        const int r = m0 + ((i < 4) ? (ty * 4 + i) : (64 + ty * 4 + i - 4));
        #pragma unroll
        for (int j = 0; j < 8; j++) {
            const int c = n0 + ((j < 4) ? (tx * 4 + j) : (64 + tx * 4 + j - 4));
            if (c < N) {
                float v = acc[i][j] + bias[c];
                C[(size_t)r * ldc + c] = softplus_f(v);
            }
        }
    }
}

// ---------------------------------------------------------------------------
// Depthwise causal conv (DC=4) + bias + SiLU — l-vectorized (R13-proven).
// ---------------------------------------------------------------------------
__global__ void conv_silu_kernel(const float* __restrict__ xz,
                                 const float* __restrict__ w,
                                 const float* __restrict__ cb,
                                 float* __restrict__ u)
{
    const int idx = blockIdx.x * blockDim.x + threadIdx.x;
    if (idx >= Mrows * DIn / 4) return;
    const int d   = idx & (DIn - 1);
    const int bl4 = idx >> 9;
    const int l4  = bl4 & (Ln / 4 - 1);
    const int b   = bl4 >> 10;
    const int l0  = l4 * 4;
    const int bl0 = b * Ln + l0;

    float xv[7];
    #pragma unroll
    for (int k = 0; k < 7; k++) {
        const int ll = l0 - 3 + k;
        xv[k] = (ll >= 0) ? xz[(size_t)(bl0 - 3 + k) * (2 * DIn) + d] : 0.f;
    }
    const float w0 = w[d * 4 + 0], w1 = w[d * 4 + 1];
    const float w2 = w[d * 4 + 2], w3 = w[d * 4 + 3];
    const float cbv = cb[d];

    #pragma unroll
    for (int j = 0; j < 4; j++) {
        float acc = cbv;
        acc = fmaf(w0, xv[j + 0], acc);
        acc = fmaf(w1, xv[j + 1], acc);
        acc = fmaf(w2, xv[j + 2], acc);
        acc = fmaf(w3, xv[j + 3], acc);
        u[(size_t)(bl0 + j) * DIn + d] = silu_f(acc);
    }
}

// ---------------------------------------------------------------------------
// LayerNorm warp-per-row (R13-proven).
// ---------------------------------------------------------------------------
__global__ void ln256_kernel(const float* __restrict__ in, float* __restrict__ out,
                             const float* __restrict__ g, const float* __restrict__ b)
{
    const int warp = threadIdx.x >> 5;
    const int lane = threadIdx.x & 31;
    const int row  = blockIdx.x * 8 + warp;
    const float* r = in + (size_t)row * 256;

    float4 v0 = *(const float4*)(r + lane * 4);
    float4 v1 = *(const float4*)(r + 128 + lane * 4);

    float s  = v0.x + v0.y + v0.z + v0.w + v1.x + v1.y + v1.z + v1.w;
    float sq = v0.x * v0.x + v0.y * v0.y + v0.z * v0.z + v0.w * v0.w
             + v1.x * v1.x + v1.y * v1.y + v1.z * v1.z + v1.w * v1.w;
    #pragma unroll
    for (int o = 16; o > 0; o >>= 1) {
        s  += __shfl_xor_sync(~0u, s, o);
        sq += __shfl_xor_sync(~0u, sq, o);
    }
    const float mean = s * (1.f / 256.f);
    const float var  = sq * (1.f / 256.f) - mean * mean;
    const float rstd = rsqrtf(var + 1e-5f);

    const float4 g0 = *(const float4*)(g + lane * 4);
    const float4 g1 = *(const float4*)(g + 128 + lane * 4);
    const float4 b0 = *(const float4*)(b + lane * 4);
    const float4 b1 = *(const float4*)(b + 128 + lane * 4);

    float4 o0, o1;
    o0.x = (v0.x - mean) * rstd * g0.x + b0.x;
    o0.y = (v0.y - mean) * rstd * g0.y + b0.y;
    o0.z = (v0.z - mean) * rstd * g0.z + b0.z;
    o0.w = (v0.w - mean) * rstd * g0.w + b0.w;
    o1.x = (v1.x - mean) * rstd * g1.x + b1.x;
    o1.y = (v1.y - mean) * rstd * g1.y + b1.y;
    o1.z = (v1.z - mean) * rstd * g1.z + b1.z;
    o1.w = (v1.w - mean) * rstd * g1.w + b1.w;

    float* ro = out + (size_t)row * 256;
    *(float4*)(ro + lane * 4)       = o0;
    *(float4*)(ro + 128 + lane * 4) = o1;
}

// ---------------------------------------------------------------------------
// Selective scan, thread-per-d (R11/R12-proven), C_CHUNKS=64.
// ---------------------------------------------------------------------------
#define SCH2 16

__global__ void __launch_bounds__(128) scan_carry_kernel(
    const float* __restrict__ u, const float* __restrict__ dt,
    const float* __restrict__ xdbc, const float* __restrict__ A_log,
    float* __restrict__ Pout, float* __restrict__ h0out)
{
    __shared__ float s_dt[SCH2][128], s_u[SCH2][128];
    __shared__ float s_B[SCH2][16];

    const int tid = threadIdx.x;
    const int c   = blockIdx.x >> 5;          // 0..C-2
    const int rem = blockIdx.x & 31;
    const int b   = rem >> 2;
    const int dg  = rem & 3;
    const int d   = dg * 128 + tid;

    float A2[16];
    #pragma unroll
    for (int s = 0; s < 16; s++)
        A2[s] = -__expf(A_log[d * 16 + s]) * LOG2E;

    float P[16], h[16];
    #pragma unroll
    for (int s = 0; s < 16; s++) { P[s] = 1.f; h[s] = 0.f; }

    const size_t base_bl = (size_t)b * Ln + (size_t)c * CH_LEN;
    const int doff = dg * 128;

    for (int l0 = 0; l0 < CH_LEN; l0 += SCH2) {
        #pragma unroll
        for (int r = 0; r < SCH2; r++) {
            const size_t bl = base_bl + l0 + r;
            s_dt[r][tid] = dt[bl * DIn + doff + tid];
            s_u [r][tid] = u [bl * DIn + doff + tid];
        }
        for (int i = tid; i < SCH2 * 16; i += 128) {
            const int r = i >> 4, cc = i & 15;
            s_B[r][cc] = xdbc[(base_bl + l0 + r) * 48 + 16 + cc];
        }
        __syncthreads();

        for (int i = 0; i < SCH2; i++) {
            const float dtv = s_dt[i][tid];
            const float x   = dtv * s_u[i][tid];
            float Bv[16];
            *(float4*)&Bv[0]  = *(const float4*)&s_B[i][0];
            *(float4*)&Bv[4]  = *(const float4*)&s_B[i][4];
            *(float4*)&Bv[8]  = *(const float4*)&s_B[i][8];
            *(float4*)&Bv[12] = *(const float4*)&s_B[i][12];
            #pragma unroll
            for (int s = 0; s < 16; s++) {
                const float dA = ex2f(dtv * A2[s]);
                P[s] *= dA;
                h[s] = fmaf(h[s], dA, x * Bv[s]);
            }
        }
        __syncthreads();
    }

    const size_t chb = (size_t)(b * DIn + d) * DSn;
    #pragma unroll
    for (int s = 0; s < 16; s++) {
        Pout [(size_t)c * NCH + chb + s] = P[s];
        h0out[(size_t)c * NCH + chb + s] = h[s];
    }
}

__global__ void scan_fix_kernel(const float* __restrict__ P,
                                const float* __restrict__ h0,
                                float* __restrict__ hini)
{
    const int ch = blockIdx.x * blockDim.x + threadIdx.x;
    float h = 0.f;
    hini[ch] = 0.f;
    #pragma unroll 4
    for (int c = 1; c < C_CHUNKS; c++) {
        h = fmaf(P[(size_t)(c - 1) * NCH + ch], h, h0[(size_t)(c - 1) * NCH + ch]);
        hini[(size_t)c * NCH + ch] = h;
    }
}

__global__ void __launch_bounds__(128) scan_main_kernel(
    const float* __restrict__ u, const float* __restrict__ dt,
    const float* __restrict__ xz, const float* __restrict__ xdbc,
    const float* __restrict__ A_log, const float* __restrict__ Dp,
    const float* __restrict__ hini,
    float* __restrict__ y)
{
    __shared__ float s_dt[SCH2][128], s_u[SCH2][128], s_z[SCH2][128];
    __shared__ float s_B[SCH2][16], s_C[SCH2][16];

    const int tid = threadIdx.x;
    const int c   = blockIdx.x >> 5;          // 0..C-1
    const int rem = blockIdx.x & 31;
    const int b   = rem >> 2;
    const int dg  = rem & 3;
    const int d   = dg * 128 + tid;

    float A2[16];
    #pragma unroll
    for (int s = 0; s < 16; s++)
        A2[s] = -__expf(A_log[d * 16 + s]) * LOG2E;
    const float dpv = Dp[d];

    const size_t chb = (size_t)(b * DIn + d) * DSn;
    float h[16];
    *(float4*)&h[0]  = *(const float4*)&hini[(size_t)c * NCH + chb];
    *(float4*)&h[4]  = *(const float4*)&hini[(size_t)c * NCH + chb + 4];
    *(float4*)&h[8]  = *(const float4*)&hini[(size_t)c * NCH + chb + 8];
    *(float4*)&h[12] = *(const float4*)&hini[(size_t)c * NCH + chb + 12];

    const size_t base_bl = (size_t)b * Ln + (size_t)c * CH_LEN;
    const int doff = dg * 128;

    for (int l0 = 0; l0 < CH_LEN; l0 += SCH2) {
        #pragma unroll
        for (int r = 0; r < SCH2; r++) {
            const size_t bl = base_bl + l0 + r;
            s_dt[r][tid] = dt[bl * DIn + doff + tid];
            s_u [r][tid] = u [bl * DIn + doff + tid];
            s_z [r][tid] = xz[bl * (2 * DIn) + DIn + doff + tid];
        }
        for (int i = tid; i < SCH2 * 16; i += 128) {
            const int r = i >> 4, cc = i & 15;
            const size_t bl = base_bl + l0 + r;
            s_B[r][cc] = xdbc[bl * 48 + 16 + cc];
            s_C[r][cc] = xdbc[bl * 48 + 32 + cc];
        }
        __syncthreads();

        for (int i = 0; i < SCH2; i++) {
            const float dtv = s_dt[i][tid];
            const float uv  = s_u[i][tid];
            const float zv  = s_z[i][tid];
            const float x   = dtv * uv;
            float Bv[16], Cv[16];
            *(float4*)&Bv[0]  = *(const float4*)&s_B[i][0];
            *(float4*)&Bv[4]  = *(const float4*)&s_B[i][4];
            *(float4*)&Bv[8]  = *(const float4*)&s_B[i][8];
            *(float4*)&Bv[12] = *(const float4*)&s_B[i][12];
            *(float4*)&Cv[0]  = *(const float4*)&s_C[i][0];
            *(float4*)&Cv[4]  = *(const float4*)&s_C[i][4];
            *(float4*)&Cv[8]  = *(const float4*)&s_C[i][8];
            *(float4*)&Cv[12] = *(const float4*)&s_C[i][12];
            float yv = 0.f;
            #pragma unroll
            for (int s = 0; s < 16; s++) {
                const float dA = ex2f(dtv * A2[s]);
                h[s] = fmaf(h[s], dA, x * Bv[s]);
                yv = fmaf(h[s], Cv[s], yv);
            }
            yv = (yv + uv * dpv) * silu_f(zv);
            y[(base_bl + l0 + i) * DIn + doff + tid] = yv;
        }
        __syncthreads();
    }
}

// ---------------------------------------------------------------------------
// Pooling (split, R4-proven).
// ---------------------------------------------------------------------------
__global__ void pool_logit_kernel(const float* __restrict__ h,
                                  const float* __restrict__ wa,
                                  const float* __restrict__ ba,
                                  float* __restrict__ logit)
{
    const int wid_in_blk = threadIdx.x >> 5;
    const int lane = threadIdx.x & 31;
    const int row = blockIdx.x * 8 + wid_in_blk;
    const float* r = h + (size_t)row * 256;
    float acc = 0.f;
    #pragma unroll
    for (int k = 0; k < 2; k++) {
        const float4 hv = *(const float4*)(r + k * 128 + lane * 4);
        const float4 wv = *(const float4*)(wa + k * 128 + lane * 4);
        acc += hv.x * wv.x + hv.y * wv.y + hv.z * wv.z + hv.w * wv.w;
    }
    #pragma unroll
    for (int o = 16; o > 0; o >>= 1) acc += __shfl_xor_sync(~0u, acc, o);
    if (lane == 0) logit[row] = acc + ba[0];
}

__global__ void __launch_bounds__(1024) pool_softmax_kernel(float* __restrict__ logit)
{
    __shared__ float s_red[32];
    const int b = blockIdx.x, tid = threadIdx.x;
    float* lg = logit + b * Ln;

    float mx = -1e30f;
    float v[4];
    #pragma unroll
    for (int k = 0; k < 4; k++) {
        v[k] = lg[tid + k * 1024];
        mx = fmaxf(mx, v[k]);
    }
    #pragma unroll
    for (int o = 16; o > 0; o >>= 1) mx = fmaxf(mx, __shfl_xor_sync(~0u, mx, o));
    if ((tid & 31) == 0) s_red[tid >> 5] = mx;
    __syncthreads();
    if (tid < 32) {
        float t = s_red[tid];
        #pragma unroll
        for (int o = 16; o > 0; o >>= 1) t = fmaxf(t, __shfl_xor_sync(~0u, t, o));
        s_red[tid] = t;
    }
    __syncthreads();
    mx = s_red[0];
    __syncthreads();

    float sum = 0.f;
    #pragma unroll
    for (int k = 0; k < 4; k++) {
        v[k] = __expf(v[k] - mx);
        sum += v[k];
    }
    #pragma unroll
    for (int o = 16; o > 0; o >>= 1) sum += __shfl_xor_sync(~0u, sum, o);
    if ((tid & 31) == 0) s_red[tid >> 5] = sum;
    __syncthreads();
    if (tid < 32) {
        float t = s_red[tid];
        #pragma unroll
        for (int o = 16; o > 0; o >>= 1) t += __shfl_xor_sync(~0u, t, o);
        s_red[tid] = t;
    }
    __syncthreads();
    const float inv = 1.f / s_red[0];
    #pragma unroll
    for (int k = 0; k < 4; k++) lg[tid + k * 1024] = v[k] * inv;
}

__global__ void pool_wsum_kernel(const float* __restrict__ h,
                                 const float* __restrict__ p,
                                 float* __restrict__ part)
{
    const int b = blockIdx.x >> 4;
    const int sp = blockIdx.x & 15;
    const int tid = threadIdx.x;
    const size_t base = ((size_t)b * Ln + sp * 256) * 256;
    const float* pp = p + b * Ln + sp * 256;
    float acc = 0.f;
    for (int l = 0; l < 256; l++)
        acc = fmaf(pp[l], h[base + (size_t)l * 256 + tid], acc);
    part[(size_t)(b * 16 + sp) * 256 + tid] = acc;
}

__global__ void pool_final_kernel(const float* __restrict__ part,
                                  const float* __restrict__ Wf,
                                  const float* __restrict__ bf,
                                  float* __restrict__ out)
{
    __shared__ float s_red[8];
    const int b = blockIdx.x, tid = threadIdx.x;
    float pooled = 0.f;
    #pragma unroll
    for (int sp = 0; sp < 16; sp++)
        pooled += part[(size_t)(b * 16 + sp) * 256 + tid];
    float val = pooled * Wf[tid];
    #pragma unroll
    for (int o = 16; o > 0; o >>= 1) val += __shfl_xor_sync(~0u, val, o);
    if ((tid & 31) == 0) s_red[tid >> 5] = val;
    __syncthreads();
    if (tid == 0) {
        float tot = 0.f;
        #pragma unroll
        for (int i = 0; i < 8; i++) tot += s_red[i];
        out[b] = tot + bf[0];
    }
}

// ---------------------------------------------------------------------------
// Launch
// ---------------------------------------------------------------------------
extern "C" void kernel_launch(void* const* d_in, const int* in_sizes, int n_in,
                              void* d_out, int out_size)
{
    const float* x      = (const float*)d_in[0];
    const float* Wp     = (const float*)d_in[1];
    const float* bp     = (const float*)d_in[2];
    const float* g0     = (const float*)d_in[3];
    const float* b0     = (const float*)d_in[4];
    const float* Wi     = (const float*)d_in[5];
    const float* conv_w = (const float*)d_in[6];
    const float* conv_b = (const float*)d_in[7];
    const float* Wx     = (const float*)d_in[8];
    const float* Wdt    = (const float*)d_in[9];
    const float* bdt    = (const float*)d_in[10];
    const float* A_log  = (const float*)d_in[11];
    const float* Dp     = (const float*)d_in[12];
    const float* Wo     = (const float*)d_in[13];
    const float* ln_g   = (const float*)d_in[14];
    const float* ln_b   = (const float*)d_in[15];
    const float* wa     = (const float*)d_in[16];
    const float* ba     = (const float*)d_in[17];
    const float* Wf     = (const float*)d_in[18];
    const float* bf     = (const float*)d_in[19];

    float *p_h, *p_t0, *p_xz, *p_u, *p_dt, *p_xdbc, *p_y;
    float *p_P, *p_h0, *p_hini, *p_logit, *p_part;
    cudaGetSymbolAddress((void**)&p_h,    g_h);
    cudaGetSymbolAddress((void**)&p_t0,   g_t0);
    cudaGetSymbolAddress((void**)&p_xz,   g_xz);
    cudaGetSymbolAddress((void**)&p_u,    g_u);
    cudaGetSymbolAddress((void**)&p_dt,   g_dt);
    cudaGetSymbolAddress((void**)&p_xdbc, g_xdbc);
    cudaGetSymbolAddress((void**)&p_y,    g_y);
    cudaGetSymbolAddress((void**)&p_P,    g_P);
    cudaGetSymbolAddress((void**)&p_h0,   g_h0);
    cudaGetSymbolAddress((void**)&p_hini, g_hini);
    cudaGetSymbolAddress((void**)&p_logit, g_logit);
    cudaGetSymbolAddress((void**)&p_part, g_part);

    // input projection + bias (tensor tf32) + LN
    tf32_gemm<1><<<dim3(2, 256), 256>>>(Dn, DINn, x, DINn, Wp, bp, p_t0, Dn);
    ln256_kernel<<<Mrows / 8, 256>>>(p_t0, p_h, g0, b0);

    for (int l = 0; l < NLn; l++) {
        // xz = h @ Wi^T  (N=1024, K=256)
        tf32_gemm<0><<<dim3(8, 256), 256>>>(2 * DIn, Dn, p_h, Dn,
                                            Wi + (size_t)l * 2 * DIn * Dn,
                                            nullptr, p_xz, 2 * DIn);
        // depthwise causal conv + silu (l-vectorized)
        conv_silu_kernel<<<(Mrows * DIn / 4) / 256, 256>>>(
            p_xz, conv_w + (size_t)l * DIn * DCn, conv_b + (size_t)l * DIn, p_u);
        // xdbc = u @ Wx^T  (N=48, K=512)
        tf32_gemm<0><<<dim3(1, 256), 256>>>(48, DIn, p_u, DIn,
                                            Wx + (size_t)l * 48 * DIn,
                                            nullptr, p_xdbc, 48);
        // dt = softplus(dtraw @ Wdt^T + bdt)
        sgemm_dt<<<dim3(4, 256), 256>>>(DIn, DTRn, p_xdbc, 48,
                                        Wdt + (size_t)l * DIn * DTRn,
                                        bdt + (size_t)l * DIn, p_dt, DIn);
        // chunked selective scan (thread-per-d, C=64)
        scan_carry_kernel<<<32 * (C_CHUNKS - 1), 128>>>(
            p_u, p_dt, p_xdbc, A_log + (size_t)l * DIn * DSn, p_P, p_h0);
        scan_fix_kernel<<<NCH / 256, 256>>>(p_P, p_h0, p_hini);
        scan_main_kernel<<<32 * C_CHUNKS, 128>>>(
            p_u, p_dt, p_xz, p_xdbc,
            A_log + (size_t)l * DIn * DSn, Dp + (size_t)l * DIn,
            p_hini, p_y);
        // out = y @ Wo^T  (N=256, K=512), then LN
        tf32_gemm<0><<<dim3(2, 256), 256>>>(Dn, DIn, p_y, DIn,
                                            Wo + (size_t)l * Dn * DIn,
                                            nullptr, p_t0, Dn);
        ln256_kernel<<<Mrows / 8, 256>>>(p_t0, p_h,
                                         ln_g + (size_t)l * Dn, ln_b + (size_t)l * Dn);
    }

    // pooling + final linear
    pool_logit_kernel<<<Mrows / 8, 256>>>(p_h, wa, ba, p_logit);
    pool_softmax_kernel<<<Bn, 1024>>>(p_logit);
    pool_wsum_kernel<<<Bn * 16, 256>>>(p_h, p_logit, p_part);
    pool_final_kernel<<<Bn, 256>>>(p_part, Wf, bf, (float*)d_out);
}

// round 16
// speedup vs baseline: 1.1238x; 1.0003x over previous
#include <cuda_runtime.h>
#include <cuda_fp16.h>
#include <math.h>
#include <stdint.h>

// Problem constants
#define Bn   8
#define Ln   4096
#define DINn 64
#define Dn   256
#define NLn  2
#define DIn  512
#define DSn  16
#define DCn  4
#define DTRn 16
#define Mrows (Bn * Ln)   // 32768

#define C_CHUNKS 32
#define CH_LEN   128      // Ln / C_CHUNKS
#define NCH      (Bn * DIn * DSn)   // 65536

// ---------------------------------------------------------------------------
// Scratch (device globals — no runtime allocation allowed)
// ---------------------------------------------------------------------------
__device__ float  g_h    [Mrows * Dn];
__device__ float  g_t0   [Mrows * Dn];
__device__ float  g_xz   [Mrows * 2 * DIn];
__device__ __half g_zh   [Mrows * DIn];
__device__ float  g_u    [Mrows * DIn];
__device__ float  g_dt   [Mrows * DIn];
__device__ float  g_xdbc [Mrows * 48];
__device__ __half g_yh   [Mrows * DIn];
__device__ float  g_P    [(C_CHUNKS - 1) * NCH];
__device__ float  g_h0   [(C_CHUNKS - 1) * NCH];
__device__ float  g_hini [C_CHUNKS * NCH];
__device__ float  g_logit[Mrows];
__device__ float  g_part [Bn * 16 * Dn];

// ---------------------------------------------------------------------------
// Helpers
// ---------------------------------------------------------------------------
__device__ __forceinline__ float softplus_f(float x) {
    return fmaxf(x, 0.f) + log1pf(__expf(-fabsf(x)));
}
__device__ __forceinline__ float silu_f(float x) {
    return x / (1.f + __expf(-x));
}
__device__ __forceinline__ float to_tf32(float x) {
    float r;
    asm("cvt.rna.tf32.f32 %0, %1;" : "=f"(r) : "f"(x));
    return r;
}
__device__ __forceinline__ float ex2f(float x) {
    float r;
    asm("ex2.approx.ftz.f32 %0, %1;" : "=f"(r) : "f"(x));
    return r;
}
#define LOG2E 1.4426950408889634f
__device__ __forceinline__ void mma8(float* d,
                                     float a0, float a1, float a2, float a3,
                                     float b0, float b1) {
    asm volatile(
        "mma.sync.aligned.m16n8k8.row.col.f32.tf32.tf32.f32 "
        "{%0,%1,%2,%3},{%4,%5,%6,%7},{%8,%9},{%0,%1,%2,%3};"
        : "+f"(d[0]), "+f"(d[1]), "+f"(d[2]), "+f"(d[3])
        : "r"(__float_as_uint(a0)), "r"(__float_as_uint(a1)),
          "r"(__float_as_uint(a2)), "r"(__float_as_uint(a3)),
          "r"(__float_as_uint(b0)), "r"(__float_as_uint(b1)));
}

// ---------------------------------------------------------------------------
// TF32 tensor-core GEMM (R4-proven, 128x128 tile).
// EPI: 0 store, 1 +bias, 2 = xz split (cols < DIn -> C fp32, cols >= DIn ->
//      zh as fp16 at column c-DIn).
// ---------------------------------------------------------------------------
#define SPAD 24
template <int EPI>
__global__ void __launch_bounds__(256, 2) tf32_gemm(
    int N, int K,
    const float* __restrict__ A, int lda,
    const float* __restrict__ W,
    const float* __restrict__ bias,
    float* __restrict__ C, int ldc,
    __half* __restrict__ zh)
{
    __shared__ float As[2][128][SPAD];
    __shared__ float Ws[2][128][SPAD];

    const int tid  = threadIdx.x;
    const int wid  = tid >> 5, lane = tid & 31;
    const int wm   = (wid >> 2) * 64;
    const int wn   = (wid & 3) * 32;
    const int gr   = lane >> 2;
    const int gc   = lane & 3;
    const int m0   = blockIdx.y * 128;
    const int n0   = blockIdx.x * 128;

    const int lr0 = tid >> 2;
    const int lj  = tid & 3;
    const int pb  = (lj & 2) * 4 + (lj & 1);

    const float* Ag = A + (size_t)(m0 + lr0) * lda + lj * 4;
    const float* Wg = W + (size_t)(n0 + lr0) * K + lj * 4;
    const bool wok0 = (n0 + lr0) < N;
    const bool wok1 = (n0 + lr0 + 64) < N;

    float acc[4][4][4];
    #pragma unroll
    for (int i = 0; i < 4; i++)
        #pragma unroll
        for (int j = 0; j < 4; j++)
            #pragma unroll
            for (int t = 0; t < 4; t++) acc[i][j][t] = 0.f;

    float4 ra0, ra1, rw0, rw1;
    const float4 z4 = make_float4(0.f, 0.f, 0.f, 0.f);

    ra0 = *(const float4*)(Ag);
    ra1 = *(const float4*)(Ag + (size_t)64 * lda);
    rw0 = wok0 ? *(const float4*)(Wg) : z4;
    rw1 = wok1 ? *(const float4*)(Wg + (size_t)64 * K) : z4;
    {
        As[0][lr0     ][pb]     = to_tf32(ra0.x);
        As[0][lr0     ][pb + 2] = to_tf32(ra0.y);
        As[0][lr0     ][pb + 4] = to_tf32(ra0.z);
        As[0][lr0     ][pb + 6] = to_tf32(ra0.w);
        As[0][lr0 + 64][pb]     = to_tf32(ra1.x);
        As[0][lr0 + 64][pb + 2] = to_tf32(ra1.y);
        As[0][lr0 + 64][pb + 4] = to_tf32(ra1.z);
        As[0][lr0 + 64][pb + 6] = to_tf32(ra1.w);
        Ws[0][lr0     ][pb]     = to_tf32(rw0.x);
        Ws[0][lr0     ][pb + 2] = to_tf32(rw0.y);
        Ws[0][lr0     ][pb + 4] = to_tf32(rw0.z);
        Ws[0][lr0     ][pb + 6] = to_tf32(rw0.w);
        Ws[0][lr0 + 64][pb]     = to_tf32(rw1.x);
        Ws[0][lr0 + 64][pb + 2] = to_tf32(rw1.y);
        Ws[0][lr0 + 64][pb + 4] = to_tf32(rw1.z);
        Ws[0][lr0 + 64][pb + 6] = to_tf32(rw1.w);
    }
    __syncthreads();

    int buf = 0;
    for (int k0 = 16; k0 < K; k0 += 16) {
        ra0 = *(const float4*)(Ag + k0);
        ra1 = *(const float4*)(Ag + (size_t)64 * lda + k0);
        rw0 = wok0 ? *(const float4*)(Wg + k0) : z4;
        rw1 = wok1 ? *(const float4*)(Wg + (size_t)64 * K + k0) : z4;

        #pragma unroll
        for (int ks = 0; ks < 2; ks++) {
            float2 alo[4], ahi[4], bfr[4];
            #pragma unroll
            for (int fm = 0; fm < 4; fm++) {
                alo[fm] = *(const float2*)&As[buf][wm + fm * 16 + gr    ][ks * 8 + 2 * gc];
                ahi[fm] = *(const float2*)&As[buf][wm + fm * 16 + gr + 8][ks * 8 + 2 * gc];
            }
            #pragma unroll
            for (int fn = 0; fn < 4; fn++)
                bfr[fn] = *(const float2*)&Ws[buf][wn + fn * 8 + gr][ks * 8 + 2 * gc];
            #pragma unroll
            for (int fm = 0; fm < 4; fm++)
                #pragma unroll
                for (int fn = 0; fn < 4; fn++)
                    mma8(acc[fm][fn], alo[fm].x, ahi[fm].x, alo[fm].y, ahi[fm].y,
                         bfr[fn].x, bfr[fn].y);
        }

        const int nb = buf ^ 1;
        As[nb][lr0     ][pb]     = to_tf32(ra0.x);
        As[nb][lr0     ][pb + 2] = to_tf32(ra0.y);
        As[nb][lr0     ][pb + 4] = to_tf32(ra0.z);
        As[nb][lr0     ][pb + 6] = to_tf32(ra0.w);
        As[nb][lr0 + 64][pb]     = to_tf32(ra1.x);
        As[nb][lr0 + 64][pb + 2] = to_tf32(ra1.y);
        As[nb][lr0 + 64][pb + 4] = to_tf32(ra1.z);
        As[nb][lr0 + 64][pb + 6] = to_tf32(ra1.w);
        Ws[nb][lr0     ][pb]     = to_tf32(rw0.x);
        Ws[nb][lr0     ][pb + 2] = to_tf32(rw0.y);
        Ws[nb][lr0     ][pb + 4] = to_tf32(rw0.z);
        Ws[nb][lr0     ][pb + 6] = to_tf32(rw0.w);
        Ws[nb][lr0 + 64][pb]     = to_tf32(rw1.x);
        Ws[nb][lr0 + 64][pb + 2] = to_tf32(rw1.y);
        Ws[nb][lr0 + 64][pb + 4] = to_tf32(rw1.z);
        Ws[nb][lr0 + 64][pb + 6] = to_tf32(rw1.w);
        __syncthreads();
        buf = nb;
    }

    #pragma unroll
    for (int ks = 0; ks < 2; ks++) {
        float2 alo[4], ahi[4], bfr[4];
        #pragma unroll
        for (int fm = 0; fm < 4; fm++) {
            alo[fm] = *(const float2*)&As[buf][wm + fm * 16 + gr    ][ks * 8 + 2 * gc];
            ahi[fm] = *(const float2*)&As[buf][wm + fm * 16 + gr + 8][ks * 8 + 2 * gc];
        }
        #pragma unroll
        for (int fn = 0; fn < 4; fn++)
            bfr[fn] = *(const float2*)&Ws[buf][wn + fn * 8 + gr][ks * 8 + 2 * gc];
        #pragma unroll
        for (int fm = 0; fm < 4; fm++)
            #pragma unroll
            for (int fn = 0; fn < 4; fn++)
                mma8(acc[fm][fn], alo[fm].x, ahi[fm].x, alo[fm].y, ahi[fm].y,
                     bfr[fn].x, bfr[fn].y);
    }

    #pragma unroll
    for (int fm = 0; fm < 4; fm++) {
        const int r0 = m0 + wm + fm * 16 + gr;
        #pragma unroll
        for (int fn = 0; fn < 4; fn++) {
            const int c0 = n0 + wn + fn * 8 + 2 * gc;
            float v0 = acc[fm][fn][0], v1 = acc[fm][fn][1];
            float v2 = acc[fm][fn][2], v3 = acc[fm][fn][3];
            if (EPI == 1) {
                v0 += bias[c0]; v1 += bias[c0 + 1];
                v2 += bias[c0]; v3 += bias[c0 + 1];
            }
            if (EPI == 2) {
                if (c0 < DIn) {
                    *(float2*)&C[(size_t)r0 * ldc + c0]       = make_float2(v0, v1);
                    *(float2*)&C[(size_t)(r0 + 8) * ldc + c0] = make_float2(v2, v3);
                } else {
                    const int cz = c0 - DIn;
                    *(__half2*)&zh[(size_t)r0 * DIn + cz] =
                        __floats2half2_rn(v0, v1);
                    *(__half2*)&zh[(size_t)(r0 + 8) * DIn + cz] =
                        __floats2half2_rn(v2, v3);
                }
            } else {
                if (c0 < N) {
                    *(float2*)&C[(size_t)r0 * ldc + c0]       = make_float2(v0, v1);
                    *(float2*)&C[(size_t)(r0 + 8) * ldc + c0] = make_float2(v2, v3);
                }
            }
        }
    }
}

// ---------------------------------------------------------------------------
// TF32 GEMM with fp16 A operand (for Wo: A = y in half).  Same structure.
// N%128==0 here (N=256).  EPI 0 only.
// ---------------------------------------------------------------------------
__global__ void __launch_bounds__(256, 2) tf32_gemm_ha(
    int N, int K,
    const __half* __restrict__ A, int lda,
    const float* __restrict__ W,
    float* __restrict__ C, int ldc)
{
    __shared__ float As[2][128][SPAD];
    __shared__ float Ws[2][128][SPAD];

    const int tid  = threadIdx.x;
    const int wid  = tid >> 5, lane = tid & 31;
    const int wm   = (wid >> 2) * 64;
    const int wn   = (wid & 3) * 32;
    const int gr   = lane >> 2;
    const int gc   = lane & 3;
    const int m0   = blockIdx.y * 128;
    const int n0   = blockIdx.x * 128;

    const int lr0 = tid >> 2;
    const int lj  = tid & 3;
    const int pb  = (lj & 2) * 4 + (lj & 1);

    const __half* Ag = A + (size_t)(m0 + lr0) * lda + lj * 4;
    const float*  Wg = W + (size_t)(n0 + lr0) * K + lj * 4;

    float acc[4][4][4];
    #pragma unroll
    for (int i = 0; i < 4; i++)
        #pragma unroll
        for (int j = 0; j < 4; j++)
            #pragma unroll
            for (int t = 0; t < 4; t++) acc[i][j][t] = 0.f;

    float4 ra0, ra1, rw0, rw1;

    {
        __half2 a0 = *(const __half2*)(Ag);
        __half2 a1 = *(const __half2*)(Ag + 2);
        __half2 b0 = *(const __half2*)(Ag + (size_t)64 * lda);
        __half2 b1 = *(const __half2*)(Ag + (size_t)64 * lda + 2);
        float2 f0 = __half22float2(a0), f1 = __half22float2(a1);
        float2 f2 = __half22float2(b0), f3 = __half22float2(b1);
        ra0 = make_float4(f0.x, f0.y, f1.x, f1.y);
        ra1 = make_float4(f2.x, f2.y, f3.x, f3.y);
    }
    rw0 = *(const float4*)(Wg);
    rw1 = *(const float4*)(Wg + (size_t)64 * K);
    {
        As[0][lr0     ][pb]     = to_tf32(ra0.x);
        As[0][lr0     ][pb + 2] = to_tf32(ra0.y);
        As[0][lr0     ][pb + 4] = to_tf32(ra0.z);
        As[0][lr0     ][pb + 6] = to_tf32(ra0.w);
        As[0][lr0 + 64][pb]     = to_tf32(ra1.x);
        As[0][lr0 + 64][pb + 2] = to_tf32(ra1.y);
        As[0][lr0 + 64][pb + 4] = to_tf32(ra1.z);
        As[0][lr0 + 64][pb + 6] = to_tf32(ra1.w);
        Ws[0][lr0     ][pb]     = to_tf32(rw0.x);
        Ws[0][lr0     ][pb + 2] = to_tf32(rw0.y);
        Ws[0][lr0     ][pb + 4] = to_tf32(rw0.z);
        Ws[0][lr0     ][pb + 6] = to_tf32(rw0.w);
        Ws[0][lr0 + 64][pb]     = to_tf32(rw1.x);
        Ws[0][lr0 + 64][pb + 2] = to_tf32(rw1.y);
        Ws[0][lr0 + 64][pb + 4] = to_tf32(rw1.z);
        Ws[0][lr0 + 64][pb + 6] = to_tf32(rw1.w);
    }
    __syncthreads();

    int buf = 0;
    for (int k0 = 16; k0 < K; k0 += 16) {
        {
            __half2 a0 = *(const __half2*)(Ag + k0);
            __half2 a1 = *(const __half2*)(Ag + k0 + 2);
            __half2 b0 = *(const __half2*)(Ag + (size_t)64 * lda + k0);
            __half2 b1 = *(const __half2*)(Ag + (size_t)64 * lda + k0 + 2);
            float2 f0 = __half22float2(a0), f1 = __half22float2(a1);
            float2 f2 = __half22float2(b0), f3 = __half22float2(b1);
            ra0 = make_float4(f0.x, f0.y, f1.x, f1.y);
            ra1 = make_float4(f2.x, f2.y, f3.x, f3.y);
        }
        rw0 = *(const float4*)(Wg + k0);
        rw1 = *(const float4*)(Wg + (size_t)64 * K + k0);

        #pragma unroll
        for (int ks = 0; ks < 2; ks++) {
            float2 alo[4], ahi[4], bfr[4];
            #pragma unroll
            for (int fm = 0; fm < 4; fm++) {
                alo[fm] = *(const float2*)&As[buf][wm + fm * 16 + gr    ][ks * 8 + 2 * gc];
                ahi[fm] = *(const float2*)&As[buf][wm + fm * 16 + gr + 8][ks * 8 + 2 * gc];
            }
            #pragma unroll
            for (int fn = 0; fn < 4; fn++)
                bfr[fn] = *(const float2*)&Ws[buf][wn + fn * 8 + gr][ks * 8 + 2 * gc];
            #pragma unroll
            for (int fm = 0; fm < 4; fm++)
                #pragma unroll
                for (int fn = 0; fn < 4; fn++)
                    mma8(acc[fm][fn], alo[fm].x, ahi[fm].x, alo[fm].y, ahi[fm].y,
                         bfr[fn].x, bfr[fn].y);
        }

        const int nb = buf ^ 1;
        As[nb][lr0     ][pb]     = to_tf32(ra0.x);
        As[nb][lr0     ][pb + 2] = to_tf32(ra0.y);
        As[nb][lr0     ][pb + 4] = to_tf32(ra0.z);
        As[nb][lr0     ][pb + 6] = to_tf32(ra0.w);
        As[nb][lr0 + 64][pb]     = to_tf32(ra1.x);
        As[nb][lr0 + 64][pb + 2] = to_tf32(ra1.y);
        As[nb][lr0 + 64][pb + 4] = to_tf32(ra1.z);
        As[nb][lr0 + 64][pb + 6] = to_tf32(ra1.w);
        Ws[nb][lr0     ][pb]     = to_tf32(rw0.x);
        Ws[nb][lr0     ][pb + 2] = to_tf32(rw0.y);
        Ws[nb][lr0     ][pb + 4] = to_tf32(rw0.z);
        Ws[nb][lr0     ][pb + 6] = to_tf32(rw0.w);
        Ws[nb][lr0 + 64][pb]     = to_tf32(rw1.x);
        Ws[nb][lr0 + 64][pb + 2] = to_tf32(rw1.y);
        Ws[nb][lr0 + 64][pb + 4] = to_tf32(rw1.z);
        Ws[nb][lr0 + 64][pb + 6] = to_tf32(rw1.w);
        __syncthreads();
        buf = nb;
    }

    #pragma unroll
    for (int ks = 0; ks < 2; ks++) {
        float2 alo[4], ahi[4], bfr[4];
        #pragma unroll
        for (int fm = 0; fm < 4; fm++) {
            alo[fm] = *(const float2*)&As[buf][wm + fm * 16 + gr    ][ks * 8 + 2 * gc];
            ahi[fm] = *(const float2*)&As[buf][wm + fm * 16 + gr + 8][ks * 8 + 2 * gc];
        }
        #pragma unroll
        for (int fn = 0; fn < 4; fn++)
            bfr[fn] = *(const float2*)&Ws[buf][wn + fn * 8 + gr][ks * 8 + 2 * gc];
        #pragma unroll
        for (int fm = 0; fm < 4; fm++)
            #pragma unroll
            for (int fn = 0; fn < 4; fn++)
                mma8(acc[fm][fn], alo[fm].x, ahi[fm].x, alo[fm].y, ahi[fm].y,
                     bfr[fn].x, bfr[fn].y);
    }

    #pragma unroll
    for (int fm = 0; fm < 4; fm++) {
        const int r0 = m0 + wm + fm * 16 + gr;
        #pragma unroll
        for (int fn = 0; fn < 4; fn++) {
            const int c0 = n0 + wn + fn * 8 + 2 * gc;
            *(float2*)&C[(size_t)r0 * ldc + c0] =
                make_float2(acc[fm][fn][0], acc[fm][fn][1]);
            *(float2*)&C[(size_t)(r0 + 8) * ldc + c0] =
                make_float2(acc[fm][fn][2], acc[fm][fn][3]);
        }
    }
}

// ---------------------------------------------------------------------------
// SIMT SGEMM for dt (N=512, K=16). softplus(+bias) epilogue.
// ---------------------------------------------------------------------------
__global__ void __launch_bounds__(256, 2) sgemm_dt(
    int N, int K,
    const float* __restrict__ A, int lda,
    const float* __restrict__ W,
    const float* __restrict__ bias,
    float* __restrict__ C, int ldc)
{
    __shared__ __align__(16) float As[8][132];
    __shared__ __align__(16) float Ws2[8][132];

    const int tid = threadIdx.x;
    const int tx = tid & 15;
    const int ty = tid >> 4;
    const int m0 = blockIdx.y * 128;
    const int n0 = blockIdx.x * 128;

    const int lr = tid >> 1;
    const int lk = (tid & 1) * 4;

    float acc[8][8];
    #pragma unroll
    for (int i = 0; i < 8; i++)
        #pragma unroll
        for (int j = 0; j < 8; j++) acc[i][j] = 0.f;

    const float* Aptr = A + (size_t)(m0 + lr) * lda + lk;
    const int wn = n0 + lr;
    const float* Wptr = W + (size_t)wn * K + lk;
    const bool wok = (wn < N);

    for (int k0 = 0; k0 < K; k0 += 8) {
        float4 av = *(const float4*)(Aptr + k0);
        As[lk + 0][lr] = av.x; As[lk + 1][lr] = av.y;
        As[lk + 2][lr] = av.z; As[lk + 3][lr] = av.w;

        float4 wv = make_float4(0.f, 0.f, 0.f, 0.f);
        if (wok) wv = *(const float4*)(Wptr + k0);
        Ws2[lk + 0][lr] = wv.x; Ws2[lk + 1][lr] = wv.y;
        Ws2[lk + 2][lr] = wv.z; Ws2[lk + 3][lr] = wv.w;

        __syncthreads();
        #pragma unroll
        for (int k = 0; k < 8; k++) {
            float a[8], bb[8];
            *(float4*)&a[0]  = *(const float4*)&As[k][ty * 4];
            *(float4*)&a[4]  = *(const float4*)&As[k][64 + ty * 4];
            *(float4*)&bb[0] = *(const float4*)&Ws2[k][tx * 4];
            *(float4*)&bb[4] = *(const float4*)&Ws2[k][64 + tx * 4];
            #pragma unroll
            for (int i = 0; i < 8; i++)
                #pragma unroll
                for (int j = 0; j < 8; j++)
                    acc[i][j] = fmaf(a[i], bb[j], acc[i][j]);
        }
        __syncthreads();
    }

    #pragma unroll
    for (int i = 0; i < 8; i++) {
        const int r = m0 + ((i < 4) ? (ty * 4 + i) : (64 + ty * 4 + i - 4));
        #pragma unroll
        for (int j = 0; j < 8; j++) {
            const int c = n0 + ((j < 4) ? (tx * 4 + j) : (64 + tx * 4 + j - 4));
            if (c < N) {
                float v = acc[i][j] + bias[c];
                C[(size_t)r * ldc + c] = softplus_f(v);
            }
        }
    }
}

// ---------------------------------------------------------------------------
// Depthwise causal conv (DC=4) + bias + SiLU — l-vectorized (R13-proven).
// ---------------------------------------------------------------------------
__global__ void conv_silu_kernel(const float* __restrict__ xz,
                                 const float* __restrict__ w,
                                 const float* __restrict__ cb,
                                 float* __restrict__ u)
{
    const int idx = blockIdx.x * blockDim.x + threadIdx.x;
    if (idx >= Mrows * DIn / 4) return;
    const int d   = idx & (DIn - 1);
    const int bl4 = idx >> 9;
    const int l4  = bl4 & (Ln / 4 - 1);
    const int b   = bl4 >> 10;
    const int l0  = l4 * 4;
    const int bl0 = b * Ln + l0;

    float xv[7];
    #pragma unroll
    for (int k = 0; k < 7; k++) {
        const int ll = l0 - 3 + k;
        xv[k] = (ll >= 0) ? xz[(size_t)(bl0 - 3 + k) * (2 * DIn) + d] : 0.f;
    }
    const float w0 = w[d * 4 + 0], w1 = w[d * 4 + 1];
    const float w2 = w[d * 4 + 2], w3 = w[d * 4 + 3];
    const float cbv = cb[d];

    #pragma unroll
    for (int j = 0; j < 4; j++) {
        float acc = cbv;
        acc = fmaf(w0, xv[j + 0], acc);
        acc = fmaf(w1, xv[j + 1], acc);
        acc = fmaf(w2, xv[j + 2], acc);
        acc = fmaf(w3, xv[j + 3], acc);
        u[(size_t)(bl0 + j) * DIn + d] = silu_f(acc);
    }
}

// ---------------------------------------------------------------------------
// LayerNorm warp-per-row (R13-proven).
// ---------------------------------------------------------------------------
__global__ void ln256_kernel(const float* __restrict__ in, float* __restrict__ out,
                             const float* __restrict__ g, const float* __restrict__ b)
{
    const int warp = threadIdx.x >> 5;
    const int lane = threadIdx.x & 31;
    const int row  = blockIdx.x * 8 + warp;
    const float* r = in + (size_t)row * 256;

    float4 v0 = *(const float4*)(r + lane * 4);
    float4 v1 = *(const float4*)(r + 128 + lane * 4);

    float s  = v0.x + v0.y + v0.z + v0.w + v1.x + v1.y + v1.z + v1.w;
    float sq = v0.x * v0.x + v0.y * v0.y + v0.z * v0.z + v0.w * v0.w
             + v1.x * v1.x + v1.y * v1.y + v1.z * v1.z + v1.w * v1.w;
    #pragma unroll
    for (int o = 16; o > 0; o >>= 1) {
        s  += __shfl_xor_sync(~0u, s, o);
        sq += __shfl_xor_sync(~0u, sq, o);
    }
    const float mean = s * (1.f / 256.f);
    const float var  = sq * (1.f / 256.f) - mean * mean;
    const float rstd = rsqrtf(var + 1e-5f);

    const float4 g0 = *(const float4*)(g + lane * 4);
    const float4 g1 = *(const float4*)(g + 128 + lane * 4);
    const float4 b0 = *(const float4*)(b + lane * 4);
    const float4 b1 = *(const float4*)(b + 128 + lane * 4);

    float4 o0, o1;
    o0.x = (v0.x - mean) * rstd * g0.x + b0.x;
    o0.y = (v0.y - mean) * rstd * g0.y + b0.y;
    o0.z = (v0.z - mean) * rstd * g0.z + b0.z;
    o0.w = (v0.w - mean) * rstd * g0.w + b0.w;
    o1.x = (v1.x - mean) * rstd * g1.x + b1.x;
    o1.y = (v1.y - mean) * rstd * g1.y + b1.y;
    o1.z = (v1.z - mean) * rstd * g1.z + b1.z;
    o1.w = (v1.w - mean) * rstd * g1.w + b1.w;

    float* ro = out + (size_t)row * 256;
    *(float4*)(ro + lane * 4)       = o0;
    *(float4*)(ro + 128 + lane * 4) = o1;
}

// ---------------------------------------------------------------------------
// Selective scan, thread-per-d (R11/R12-proven), C_CHUNKS=32.
// z read as fp16, y written as fp16.
// ---------------------------------------------------------------------------
#define SCH2 16

__global__ void __launch_bounds__(128) scan_carry_kernel(
    const float* __restrict__ u, const float* __restrict__ dt,
    const float* __restrict__ xdbc, const float* __restrict__ A_log,
    float* __restrict__ Pout, float* __restrict__ h0out)
{
    __shared__ float s_dt[SCH2][128], s_u[SCH2][128];
    __shared__ float s_B[SCH2][16];

    const int tid = threadIdx.x;
    const int c   = blockIdx.x >> 5;          // 0..C-2
    const int rem = blockIdx.x & 31;
    const int b   = rem >> 2;
    const int dg  = rem & 3;
    const int d   = dg * 128 + tid;

    float A2[16];
    #pragma unroll
    for (int s = 0; s < 16; s++)
        A2[s] = -__expf(A_log[d * 16 + s]) * LOG2E;

    float P[16], h[16];
    #pragma unroll
    for (int s = 0; s < 16; s++) { P[s] = 1.f; h[s] = 0.f; }

    const size_t base_bl = (size_t)b * Ln + (size_t)c * CH_LEN;
    const int doff = dg * 128;

    for (int l0 = 0; l0 < CH_LEN; l0 += SCH2) {
        #pragma unroll
        for (int r = 0; r < SCH2; r++) {
            const size_t bl = base_bl + l0 + r;
            s_dt[r][tid] = dt[bl * DIn + doff + tid];
            s_u [r][tid] = u [bl * DIn + doff + tid];
        }
        for (int i = tid; i < SCH2 * 16; i += 128) {
            const int r = i >> 4, cc = i & 15;
            s_B[r][cc] = xdbc[(base_bl + l0 + r) * 48 + 16 + cc];
        }
        __syncthreads();

        for (int i = 0; i < SCH2; i++) {
            const float dtv = s_dt[i][tid];
            const float x   = dtv * s_u[i][tid];
            float Bv[16];
            *(float4*)&Bv[0]  = *(const float4*)&s_B[i][0];
            *(float4*)&Bv[4]  = *(const float4*)&s_B[i][4];
            *(float4*)&Bv[8]  = *(const float4*)&s_B[i][8];
            *(float4*)&Bv[12] = *(const float4*)&s_B[i][12];
            #pragma unroll
            for (int s = 0; s < 16; s++) {
                const float dA = ex2f(dtv * A2[s]);
                P[s] *= dA;
                h[s] = fmaf(h[s], dA, x * Bv[s]);
            }
        }
        __syncthreads();
    }

    const size_t chb = (size_t)(b * DIn + d) * DSn;
    #pragma unroll
    for (int s = 0; s < 16; s++) {
        Pout [(size_t)c * NCH + chb + s] = P[s];
        h0out[(size_t)c * NCH + chb + s] = h[s];
    }
}

__global__ void scan_fix_kernel(const float* __restrict__ P,
                                const float* __restrict__ h0,
                                float* __restrict__ hini)
{
    const int ch = blockIdx.x * blockDim.x + threadIdx.x;
    float h = 0.f;
    hini[ch] = 0.f;
    #pragma unroll 4
    for (int c = 1; c < C_CHUNKS; c++) {
        h = fmaf(P[(size_t)(c - 1) * NCH + ch], h, h0[(size_t)(c - 1) * NCH + ch]);
        hini[(size_t)c * NCH + ch] = h;
    }
}

__global__ void __launch_bounds__(128) scan_main_kernel(
    const float* __restrict__ u, const float* __restrict__ dt,
    const __half* __restrict__ zh, const float* __restrict__ xdbc,
    const float* __restrict__ A_log, const float* __restrict__ Dp,
    const float* __restrict__ hini,
    __half* __restrict__ yh)
{
    __shared__ float s_dt[SCH2][128], s_u[SCH2][128], s_z[SCH2][128];
    __shared__ float s_B[SCH2][16], s_C[SCH2][16];

    const int tid = threadIdx.x;
    const int c   = blockIdx.x >> 5;          // 0..C-1
    const int rem = blockIdx.x & 31;
    const int b   = rem >> 2;
    const int dg  = rem & 3;
    const int d   = dg * 128 + tid;

    float A2[16];
    #pragma unroll
    for (int s = 0; s < 16; s++)
        A2[s] = -__expf(A_log[d * 16 + s]) * LOG2E;
    const float dpv = Dp[d];

    const size_t chb = (size_t)(b * DIn + d) * DSn;
    float h[16];
    *(float4*)&h[0]  = *(const float4*)&hini[(size_t)c * NCH + chb];
    *(float4*)&h[4]  = *(const float4*)&hini[(size_t)c * NCH + chb + 4];
    *(float4*)&h[8]  = *(const float4*)&hini[(size_t)c * NCH + chb + 8];
    *(float4*)&h[12] = *(const float4*)&hini[(size_t)c * NCH + chb + 12];

    const size_t base_bl = (size_t)b * Ln + (size_t)c * CH_LEN;
    const int doff = dg * 128;

    for (int l0 = 0; l0 < CH_LEN; l0 += SCH2) {
        #pragma unroll
        for (int r = 0; r < SCH2; r++) {
            const size_t bl = base_bl + l0 + r;
            s_dt[r][tid] = dt[bl * DIn + doff + tid];
            s_u [r][tid] = u [bl * DIn + doff + tid];
            s_z [r][tid] = __half2float(zh[bl * DIn + doff + tid]);
        }
        for (int i = tid; i < SCH2 * 16; i += 128) {
            const int r = i >> 4, cc = i & 15;
            const size_t bl = base_bl + l0 + r;
            s_B[r][cc] = xdbc[bl * 48 + 16 + cc];
            s_C[r][cc] = xdbc[bl * 48 + 32 + cc];
        }
        __syncthreads();

        for (int i = 0; i < SCH2; i++) {
            const float dtv = s_dt[i][tid];
            const float uv  = s_u[i][tid];
            const float zv  = s_z[i][tid];
            const float x   = dtv * uv;
            float Bv[16], Cv[16];
            *(float4*)&Bv[0]  = *(const float4*)&s_B[i][0];
            *(float4*)&Bv[4]  = *(const float4*)&s_B[i][4];
            *(float4*)&Bv[8]  = *(const float4*)&s_B[i][8];
            *(float4*)&Bv[12] = *(const float4*)&s_B[i][12];
            *(float4*)&Cv[0]  = *(const float4*)&s_C[i][0];
            *(float4*)&Cv[4]  = *(const float4*)&s_C[i][4];
            *(float4*)&Cv[8]  = *(const float4*)&s_C[i][8];
            *(float4*)&Cv[12] = *(const float4*)&s_C[i][12];
            float yv = 0.f;
            #pragma unroll
            for (int s = 0; s < 16; s++) {
                const float dA = ex2f(dtv * A2[s]);
                h[s] = fmaf(h[s], dA, x * Bv[s]);
                yv = fmaf(h[s], Cv[s], yv);
            }
            yv = (yv + uv * dpv) * silu_f(zv);
            yh[(base_bl + l0 + i) * DIn + doff + tid] = __float2half(yv);
        }
        __syncthreads();
    }
}

// ---------------------------------------------------------------------------
// Pooling (split, R4-proven).
// ---------------------------------------------------------------------------
__global__ void pool_logit_kernel(const float* __restrict__ h,
                                  const float* __restrict__ wa,
                                  const float* __restrict__ ba,
                                  float* __restrict__ logit)
{
    const int wid_in_blk = threadIdx.x >> 5;
    const int lane = threadIdx.x & 31;
    const int row = blockIdx.x * 8 + wid_in_blk;
    const float* r = h + (size_t)row * 256;
    float acc = 0.f;
    #pragma unroll
    for (int k = 0; k < 2; k++) {
        const float4 hv = *(const float4*)(r + k * 128 + lane * 4);
        const float4 wv = *(const float4*)(wa + k * 128 + lane * 4);
        acc += hv.x * wv.x + hv.y * wv.y + hv.z * wv.z + hv.w * wv.w;
    }
    #pragma unroll
    for (int o = 16; o > 0; o >>= 1) acc += __shfl_xor_sync(~0u, acc, o);
    if (lane == 0) logit[row] = acc + ba[0];
}

__global__ void __launch_bounds__(1024) pool_softmax_kernel(float* __restrict__ logit)
{
    __shared__ float s_red[32];
    const int b = blockIdx.x, tid = threadIdx.x;
    float* lg = logit + b * Ln;

    float mx = -1e30f;
    float v[4];
    #pragma unroll
    for (int k = 0; k < 4; k++) {
        v[k] = lg[tid + k * 1024];
        mx = fmaxf(mx, v[k]);
    }
    #pragma unroll
    for (int o = 16; o > 0; o >>= 1) mx = fmaxf(mx, __shfl_xor_sync(~0u, mx, o));
    if ((tid & 31) == 0) s_red[tid >> 5] = mx;
    __syncthreads();
    if (tid < 32) {
        float t = s_red[tid];
        #pragma unroll
        for (int o = 16; o > 0; o >>= 1) t = fmaxf(t, __shfl_xor_sync(~0u, t, o));
        s_red[tid] = t;
    }
    __syncthreads();
    mx = s_red[0];
    __syncthreads();

    float sum = 0.f;
    #pragma unroll
    for (int k = 0; k < 4; k++) {
        v[k] = __expf(v[k] - mx);
        sum += v[k];
    }
    #pragma unroll
    for (int o = 16; o > 0; o >>= 1) sum += __shfl_xor_sync(~0u, sum, o);
    if ((tid & 31) == 0) s_red[tid >> 5] = sum;
    __syncthreads();
    if (tid < 32) {
        float t = s_red[tid];
        #pragma unroll
        for (int o = 16; o > 0; o >>= 1) t += __shfl_xor_sync(~0u, t, o);
        s_red[tid] = t;
    }
    __syncthreads();
    const float inv = 1.f / s_red[0];
    #pragma unroll
    for (int k = 0; k < 4; k++) lg[tid + k * 1024] = v[k] * inv;
}

__global__ void pool_wsum_kernel(const float* __restrict__ h,
                                 const float* __restrict__ p,
                                 float* __restrict__ part)
{
    const int b = blockIdx.x >> 4;
    const int sp = blockIdx.x & 15;
    const int tid = threadIdx.x;
    const size_t base = ((size_t)b * Ln + sp * 256) * 256;
    const float* pp = p + b * Ln + sp * 256;
    float acc = 0.f;
    for (int l = 0; l < 256; l++)
        acc = fmaf(pp[l], h[base + (size_t)l * 256 + tid], acc);
    part[(size_t)(b * 16 + sp) * 256 + tid] = acc;
}

__global__ void pool_final_kernel(const float* __restrict__ part,
                                  const float* __restrict__ Wf,
                                  const float* __restrict__ bf,
                                  float* __restrict__ out)
{
    __shared__ float s_red[8];
    const int b = blockIdx.x, tid = threadIdx.x;
    float pooled = 0.f;
    #pragma unroll
    for (int sp = 0; sp < 16; sp++)
        pooled += part[(size_t)(b * 16 + sp) * 256 + tid];
    float val = pooled * Wf[tid];
    #pragma unroll
    for (int o = 16; o > 0; o >>= 1) val += __shfl_xor_sync(~0u, val, o);
    if ((tid & 31) == 0) s_red[tid >> 5] = val;
    __syncthreads();
    if (tid == 0) {
        float tot = 0.f;
        #pragma unroll
        for (int i = 0; i < 8; i++) tot += s_red[i];
        out[b] = tot + bf[0];
    }
}

// ---------------------------------------------------------------------------
// Launch
// ---------------------------------------------------------------------------
extern "C" void kernel_launch(void* const* d_in, const int* in_sizes, int n_in,
                              void* d_out, int out_size)
{
    const float* x      = (const float*)d_in[0];
    const float* Wp     = (const float*)d_in[1];
    const float* bp     = (const float*)d_in[2];
    const float* g0     = (const float*)d_in[3];
    const float* b0     = (const float*)d_in[4];
    const float* Wi     = (const float*)d_in[5];
    const float* conv_w = (const float*)d_in[6];
    const float* conv_b = (const float*)d_in[7];
    const float* Wx     = (const float*)d_in[8];
    const float* Wdt    = (const float*)d_in[9];
    const float* bdt    = (const float*)d_in[10];
    const float* A_log  = (const float*)d_in[11];
    const float* Dp     = (const float*)d_in[12];
    const float* Wo     = (const float*)d_in[13];
    const float* ln_g   = (const float*)d_in[14];
    const float* ln_b   = (const float*)d_in[15];
    const float* wa     = (const float*)d_in[16];
    const float* ba     = (const float*)d_in[17];
    const float* Wf     = (const float*)d_in[18];
    const float* bf     = (const float*)d_in[19];

    float *p_h, *p_t0, *p_xz, *p_u, *p_dt, *p_xdbc;
    float *p_P, *p_h0, *p_hini, *p_logit, *p_part;
    __half *p_zh, *p_yh;
    cudaGetSymbolAddress((void**)&p_h,    g_h);
    cudaGetSymbolAddress((void**)&p_t0,   g_t0);
    cudaGetSymbolAddress((void**)&p_xz,   g_xz);
    cudaGetSymbolAddress((void**)&p_zh,   g_zh);
    cudaGetSymbolAddress((void**)&p_u,    g_u);
    cudaGetSymbolAddress((void**)&p_dt,   g_dt);
    cudaGetSymbolAddress((void**)&p_xdbc, g_xdbc);
    cudaGetSymbolAddress((void**)&p_yh,   g_yh);
    cudaGetSymbolAddress((void**)&p_P,    g_P);
    cudaGetSymbolAddress((void**)&p_h0,   g_h0);
    cudaGetSymbolAddress((void**)&p_hini, g_hini);
    cudaGetSymbolAddress((void**)&p_logit, g_logit);
    cudaGetSymbolAddress((void**)&p_part, g_part);

    // input projection + bias (tensor tf32) + LN
    tf32_gemm<1><<<dim3(2, 256), 256>>>(Dn, DINn, x, DINn, Wp, bp, p_t0, Dn,
                                        nullptr);
    ln256_kernel<<<Mrows / 8, 256>>>(p_t0, p_h, g0, b0);

    for (int l = 0; l < NLn; l++) {
        // xz = h @ Wi^T  (N=1024, K=256); u-half -> xz fp32, z-half -> zh fp16
        tf32_gemm<2><<<dim3(8, 256), 256>>>(2 * DIn, Dn, p_h, Dn,
                                            Wi + (size_t)l * 2 * DIn * Dn,
                                            nullptr, p_xz, 2 * DIn, p_zh);
        // depthwise causal conv + silu (l-vectorized)
        conv_silu_kernel<<<(Mrows * DIn / 4) / 256, 256>>>(
            p_xz, conv_w + (size_t)l * DIn * DCn, conv_b + (size_t)l * DIn, p_u);
        // xdbc = u @ Wx^T  (N=48, K=512)
        tf32_gemm<0><<<dim3(1, 256), 256>>>(48, DIn, p_u, DIn,
                                            Wx + (size_t)l * 48 * DIn,
                                            nullptr, p_xdbc, 48, nullptr);
        // dt = softplus(dtraw @ Wdt^T + bdt)
        sgemm_dt<<<dim3(4, 256), 256>>>(DIn, DTRn, p_xdbc, 48,
                                        Wdt + (size_t)l * DIn * DTRn,
                                        bdt + (size_t)l * DIn, p_dt, DIn);
        // chunked selective scan (thread-per-d, C=32)
        scan_carry_kernel<<<32 * (C_CHUNKS - 1), 128>>>(
            p_u, p_dt, p_xdbc, A_log + (size_t)l * DIn * DSn, p_P, p_h0);
        scan_fix_kernel<<<NCH / 256, 256>>>(p_P, p_h0, p_hini);
        scan_main_kernel<<<32 * C_CHUNKS, 128>>>(
            p_u, p_dt, p_zh, p_xdbc,
            A_log + (size_t)l * DIn * DSn, Dp + (size_t)l * DIn,
            p_hini, p_yh);
        // out = y(half) @ Wo^T  (N=256, K=512), then LN
        tf32_gemm_ha<<<dim3(2, 256), 256>>>(Dn, DIn, p_yh, DIn,
                                            Wo + (size_t)l * Dn * DIn,
                                            p_t0, Dn);
        ln256_kernel<<<Mrows / 8, 256>>>(p_t0, p_h,
                                         ln_g + (size_t)l * Dn, ln_b + (size_t)l * Dn);
    }

    // pooling + final linear
    pool_logit_kernel<<<Mrows / 8, 256>>>(p_h, wa, ba, p_logit);
    pool_softmax_kernel<<<Bn, 1024>>>(p_logit);
    pool_wsum_kernel<<<Bn * 16, 256>>>(p_h, p_logit, p_part);
    pool_final_kernel<<<Bn, 256>>>(p_part, Wf, bf, (float*)d_out);
}